// round 1
// baseline (speedup 1.0000x reference)
#include <cuda_runtime.h>
#include <cuda_bf16.h>
#include <cstddef>

// Problem constants
#define BATCH_N 4
#define T_SEQ   2048
#define NH      16
#define HD      64
#define DMODEL  1024
#define M_ROWS  (BATCH_N * T_SEQ)   // 8192

// Scratch: Q,K,V in [B,H,T,hd], ctx in [B*T, DMODEL]
__device__ float g_Q[BATCH_N * NH * T_SEQ * HD];
__device__ float g_K[BATCH_N * NH * T_SEQ * HD];
__device__ float g_V[BATCH_N * NH * T_SEQ * HD];
__device__ float g_ctx[(size_t)M_ROWS * DMODEL];

// ---------------------------------------------------------------------------
// GEMM: C = A @ W^T (+bias).  A[M,K] row-major, W[N,K] row-major.
// BM=128, BN=128, BK=8, 256 threads, 8x8 accum per thread.
// SPLIT_HEADS: write C[m][n] to [B,H,T,hd] layout instead of [m][n].
// ---------------------------------------------------------------------------
template <bool SPLIT_HEADS, bool ADD_BIAS>
__global__ void __launch_bounds__(256)
gemm_xwt(const float* __restrict__ A, const float* __restrict__ W,
         const float* __restrict__ bias, float* __restrict__ C)
{
    constexpr int Kdim = DMODEL;
    __shared__ float As[8][128];
    __shared__ float Bs[8][128];

    const int tid = threadIdx.x;
    const int m0 = blockIdx.y * 128;
    const int n0 = blockIdx.x * 128;

    const int lr = tid >> 1;           // 0..127
    const int lc = (tid & 1) * 4;      // 0 or 4

    const float* Ap = A + (size_t)(m0 + lr) * Kdim + lc;
    const float* Wp = W + (size_t)(n0 + lr) * Kdim + lc;

    const int ty = tid >> 4;   // 0..15
    const int tx = tid & 15;   // 0..15

    float acc[8][8];
#pragma unroll
    for (int i = 0; i < 8; i++)
#pragma unroll
        for (int j = 0; j < 8; j++) acc[i][j] = 0.0f;

    for (int k0 = 0; k0 < Kdim; k0 += 8) {
        float4 av = *(const float4*)(Ap + k0);
        float4 wv = *(const float4*)(Wp + k0);
        __syncthreads();
        As[lc + 0][lr] = av.x; As[lc + 1][lr] = av.y;
        As[lc + 2][lr] = av.z; As[lc + 3][lr] = av.w;
        Bs[lc + 0][lr] = wv.x; Bs[lc + 1][lr] = wv.y;
        Bs[lc + 2][lr] = wv.z; Bs[lc + 3][lr] = wv.w;
        __syncthreads();
#pragma unroll
        for (int kk = 0; kk < 8; kk++) {
            float a[8], b[8];
            *(float4*)(a)     = *(float4*)&As[kk][ty * 8];
            *(float4*)(a + 4) = *(float4*)&As[kk][ty * 8 + 4];
            *(float4*)(b)     = *(float4*)&Bs[kk][tx * 8];
            *(float4*)(b + 4) = *(float4*)&Bs[kk][tx * 8 + 4];
#pragma unroll
            for (int i = 0; i < 8; i++)
#pragma unroll
                for (int j = 0; j < 8; j++)
                    acc[i][j] += a[i] * b[j];
        }
    }

    if (SPLIT_HEADS) {
        // n -> (h, d); m -> (b, t). 128 | T_SEQ so all rows share b.
        const int bidx = m0 / T_SEQ;
        const int t0 = (m0 % T_SEQ) + ty * 8;
        const int n = n0 + tx * 8;
        const int h = n / HD;
        const int d = n % HD;          // thread's 8 cols stay in one head
        float* base = C + ((size_t)(bidx * NH + h) * T_SEQ) * HD + d;
#pragma unroll
        for (int i = 0; i < 8; i++) {
            float* dst = base + (size_t)(t0 + i) * HD;
            float4 v0 = make_float4(acc[i][0], acc[i][1], acc[i][2], acc[i][3]);
            float4 v1 = make_float4(acc[i][4], acc[i][5], acc[i][6], acc[i][7]);
            *(float4*)(dst)     = v0;
            *(float4*)(dst + 4) = v1;
        }
    } else {
        float bval[8];
        if (ADD_BIAS) {
            *(float4*)(bval)     = *(const float4*)&bias[n0 + tx * 8];
            *(float4*)(bval + 4) = *(const float4*)&bias[n0 + tx * 8 + 4];
        } else {
#pragma unroll
            for (int j = 0; j < 8; j++) bval[j] = 0.0f;
        }
#pragma unroll
        for (int i = 0; i < 8; i++) {
            const int m = m0 + ty * 8 + i;
            float* dst = C + (size_t)m * DMODEL + n0 + tx * 8;
            float4 v0 = make_float4(acc[i][0] + bval[0], acc[i][1] + bval[1],
                                    acc[i][2] + bval[2], acc[i][3] + bval[3]);
            float4 v1 = make_float4(acc[i][4] + bval[4], acc[i][5] + bval[5],
                                    acc[i][6] + bval[6], acc[i][7] + bval[7]);
            *(float4*)(dst)     = v0;
            *(float4*)(dst + 4) = v1;
        }
    }
}

// ---------------------------------------------------------------------------
// Flash attention (causal), fp32. One block = one (b, h, 64-query tile).
// 8 warps; warp w owns query rows w*8..w*8+7. Lane owns key/dim cols
// {lane, lane+32}. Online softmax; P staged through SMEM per warp.
// ---------------------------------------------------------------------------
#define KS_LD 68   // padded K-tile leading dim: conflict-free LDS.128

extern __shared__ float fa_smem[];

__global__ void __launch_bounds__(256)
flash_attn(const float* __restrict__ Q, const float* __restrict__ Kg,
           const float* __restrict__ Vg, float* __restrict__ ctx)
{
    const int qt = blockIdx.x;
    const int h  = blockIdx.y;
    const int b  = blockIdx.z;
    const int i0 = qt * 64;
    const size_t hb = ((size_t)(b * NH + h)) * T_SEQ * HD;

    float* Qs = fa_smem;                 // [64][64]
    float* Ks = Qs + 64 * 64;            // [64][KS_LD]
    float* Vs = Ks + 64 * KS_LD;         // [64][64]
    float* Ps = Vs + 64 * 64;            // [64][64] (warp-private rows)

    const int tid  = threadIdx.x;
    const int wid  = tid >> 5;
    const int lane = tid & 31;

    // Load Q tile
#pragma unroll
    for (int p = 0; p < 4; p++) {
        int idx = p * 1024 + tid * 4;
        int row = idx >> 6, col = idx & 63;
        *(float4*)&Qs[row * 64 + col] =
            *(const float4*)&Q[hb + (size_t)(i0 + row) * HD + col];
    }

    float m_run[8], l_run[8], o0[8], o1[8];
#pragma unroll
    for (int r = 0; r < 8; r++) {
        m_run[r] = -1e30f; l_run[r] = 0.0f; o0[r] = 0.0f; o1[r] = 0.0f;
    }

    const int qbase = i0 + wid * 8;

    for (int jt = 0; jt <= qt; jt++) {
        const int j0 = jt * 64;
        __syncthreads();   // also orders Q stores before first compute
#pragma unroll
        for (int p = 0; p < 4; p++) {
            int idx = p * 1024 + tid * 4;
            int row = idx >> 6, col = idx & 63;
            *(float4*)&Ks[row * KS_LD + col] =
                *(const float4*)&Kg[hb + (size_t)(j0 + row) * HD + col];
            *(float4*)&Vs[row * 64 + col] =
                *(const float4*)&Vg[hb + (size_t)(j0 + row) * HD + col];
        }
        __syncthreads();

        // S = Q K^T : lane computes cols {lane, lane+32} for its warp's 8 rows
        float s0[8], s1[8];
#pragma unroll
        for (int r = 0; r < 8; r++) { s0[r] = 0.0f; s1[r] = 0.0f; }
#pragma unroll
        for (int d = 0; d < 64; d += 4) {
            float4 ka = *(float4*)&Ks[lane * KS_LD + d];
            float4 kb = *(float4*)&Ks[(lane + 32) * KS_LD + d];
#pragma unroll
            for (int r = 0; r < 8; r++) {
                float4 qv = *(float4*)&Qs[(wid * 8 + r) * 64 + d];
                s0[r] += qv.x * ka.x + qv.y * ka.y + qv.z * ka.z + qv.w * ka.w;
                s1[r] += qv.x * kb.x + qv.y * kb.y + qv.z * kb.z + qv.w * kb.w;
            }
        }

        const bool diag = (jt == qt);
#pragma unroll
        for (int r = 0; r < 8; r++) {
            const int qi = qbase + r;
            float v0 = s0[r] * 0.125f;           // 1/sqrt(64)
            float v1 = s1[r] * 0.125f;
            if (diag) {
                if (j0 + lane > qi)       v0 = -1e30f;
                if (j0 + lane + 32 > qi)  v1 = -1e30f;
            }
            float mx = fmaxf(v0, v1);
#pragma unroll
            for (int off = 16; off; off >>= 1)
                mx = fmaxf(mx, __shfl_xor_sync(0xffffffffu, mx, off));
            const float m_new = fmaxf(m_run[r], mx);
            const float alpha = __expf(m_run[r] - m_new);
            const float p0 = __expf(v0 - m_new);
            const float p1 = __expf(v1 - m_new);
            float sum = p0 + p1;
#pragma unroll
            for (int off = 16; off; off >>= 1)
                sum += __shfl_xor_sync(0xffffffffu, sum, off);
            l_run[r] = l_run[r] * alpha + sum;
            m_run[r] = m_new;
            o0[r] *= alpha; o1[r] *= alpha;
            Ps[(wid * 8 + r) * 64 + lane]      = p0;
            Ps[(wid * 8 + r) * 64 + lane + 32] = p1;
        }
        __syncwarp();

        // O += P @ V : lane owns output dims {lane, lane+32}
#pragma unroll
        for (int c = 0; c < 64; c += 4) {
            float va0 = Vs[(c + 0) * 64 + lane];
            float va1 = Vs[(c + 1) * 64 + lane];
            float va2 = Vs[(c + 2) * 64 + lane];
            float va3 = Vs[(c + 3) * 64 + lane];
            float vb0 = Vs[(c + 0) * 64 + lane + 32];
            float vb1 = Vs[(c + 1) * 64 + lane + 32];
            float vb2 = Vs[(c + 2) * 64 + lane + 32];
            float vb3 = Vs[(c + 3) * 64 + lane + 32];
#pragma unroll
            for (int r = 0; r < 8; r++) {
                float4 p4 = *(float4*)&Ps[(wid * 8 + r) * 64 + c];
                o0[r] += p4.x * va0 + p4.y * va1 + p4.z * va2 + p4.w * va3;
                o1[r] += p4.x * vb0 + p4.y * vb1 + p4.z * vb2 + p4.w * vb3;
            }
        }
        // next-iteration __syncthreads orders Ps reuse
    }

    // Write ctx in [B*T, DMODEL] layout
#pragma unroll
    for (int r = 0; r < 8; r++) {
        const float inv = 1.0f / l_run[r];
        float* dst = ctx + (size_t)(b * T_SEQ + i0 + wid * 8 + r) * DMODEL + h * HD;
        dst[lane]      = o0[r] * inv;
        dst[lane + 32] = o1[r] * inv;
    }
}

// ---------------------------------------------------------------------------

extern "C" void kernel_launch(void* const* d_in, const int* in_sizes, int n_in,
                              void* d_out, int out_size)
{
    const float* x  = (const float*)d_in[0];
    const float* wq = (const float*)d_in[1];
    const float* wk = (const float*)d_in[2];
    const float* wv = (const float*)d_in[3];
    const float* wo = (const float*)d_in[4];
    const float* bo = (const float*)d_in[5];
    float* out = (float*)d_out;

    float *pQ, *pK, *pV, *pCtx;
    cudaGetSymbolAddress((void**)&pQ, g_Q);
    cudaGetSymbolAddress((void**)&pK, g_K);
    cudaGetSymbolAddress((void**)&pV, g_V);
    cudaGetSymbolAddress((void**)&pCtx, g_ctx);

    const int fa_smem_bytes = (64 * 64 + 64 * KS_LD + 64 * 64 + 64 * 64) * (int)sizeof(float);
    cudaFuncSetAttribute(flash_attn, cudaFuncAttributeMaxDynamicSharedMemorySize,
                         fa_smem_bytes);

    dim3 gthr(256);
    dim3 ggrid(DMODEL / 128, M_ROWS / 128);

    gemm_xwt<true, false><<<ggrid, gthr>>>(x, wq, nullptr, pQ);
    gemm_xwt<true, false><<<ggrid, gthr>>>(x, wk, nullptr, pK);
    gemm_xwt<true, false><<<ggrid, gthr>>>(x, wv, nullptr, pV);

    dim3 fgrid(T_SEQ / 64, NH, BATCH_N);
    flash_attn<<<fgrid, gthr, fa_smem_bytes>>>(pQ, pK, pV, pCtx);

    gemm_xwt<false, true><<<ggrid, gthr>>>(pCtx, wo, bo, out);
}

// round 3
// speedup vs baseline: 1.7804x; 1.7804x over previous
#include <cuda_runtime.h>
#include <cstdint>
#include <cstddef>

// Problem constants
#define BATCH_N 4
#define T_SEQ   2048
#define NH      16
#define HD      64
#define DMODEL  1024
#define M_ROWS  (BATCH_N * T_SEQ)   // 8192

// GEMM tiling (mma.sync m16n8k8 tf32)
#define BM 128
#define BN 128
#define BK 32
#define STAGES 3
#define NKT (DMODEL / BK)        // 32
#define LDP 36                   // padded leading dim (floats) -> conflict-free frags
#define STAGE_FLOATS (2 * 128 * LDP)          // A + B per stage
#define GEMM_SMEM (STAGES * STAGE_FLOATS * 4) // 110592 bytes

// Scratch
__device__ float g_Q[(size_t)BATCH_N * NH * T_SEQ * HD];
__device__ float g_K[(size_t)BATCH_N * NH * T_SEQ * HD];
__device__ float g_V[(size_t)BATCH_N * NH * T_SEQ * HD];
__device__ float g_ctx[(size_t)M_ROWS * DMODEL];
__device__ float g_xr[(size_t)M_ROWS * DMODEL];
__device__ float g_wr[4][(size_t)DMODEL * DMODEL];   // tf32-rounded weights

// ---------------------------------------------------------------------------
// Helpers
// ---------------------------------------------------------------------------
__device__ __forceinline__ uint32_t smem_u32(const void* p) {
    uint32_t a;
    asm("{ .reg .u64 t; cvta.to.shared.u64 t, %1; cvt.u32.u64 %0, t; }"
        : "=r"(a) : "l"(p));
    return a;
}
__device__ __forceinline__ float rtf32(float x) {
    uint32_t u;
    asm("cvt.rna.tf32.f32 %0, %1;" : "=r"(u) : "f"(x));
    return __uint_as_float(u);
}
__device__ __forceinline__ void cpa16(uint32_t s, const void* g) {
    asm volatile("cp.async.cg.shared.global [%0], [%1], 16;" :: "r"(s), "l"(g));
}
__device__ __forceinline__ void cpa_commit() {
    asm volatile("cp.async.commit_group;");
}
__device__ __forceinline__ void cpa_wait2() {
    asm volatile("cp.async.wait_group 2;");
}
__device__ __forceinline__ void mma_tf32(float* d, const uint32_t* a,
                                         const uint32_t* b) {
    asm volatile(
        "mma.sync.aligned.m16n8k8.row.col.f32.tf32.tf32.f32 "
        "{%0,%1,%2,%3}, {%4,%5,%6,%7}, {%8,%9}, {%0,%1,%2,%3};"
        : "+f"(d[0]), "+f"(d[1]), "+f"(d[2]), "+f"(d[3])
        : "r"(a[0]), "r"(a[1]), "r"(a[2]), "r"(a[3]), "r"(b[0]), "r"(b[1]));
}

// ---------------------------------------------------------------------------
// tf32 tensor-core GEMM: C = A @ W^T (+bias).
// A[M,K] row-major, W[N,K] row-major, both tf32-pre-rounded.
// 256 threads, warp grid 2(M) x 4(N), warp tile 64x32, BK=32.
// z-dim selects (W, C) for the fused QKV launch.
// ---------------------------------------------------------------------------
__device__ __forceinline__ void load_stage(const float* __restrict__ A,
                                           const float* __restrict__ W,
                                           int m0, int n0, int kt,
                                           uint32_t sA, uint32_t sB, int tid)
{
#pragma unroll
    for (int p = 0; p < 4; p++) {           // 1024 16B chunks / 256 thr
        int i = tid + p * 256;
        int r = i >> 3, c = i & 7;
        cpa16(sA + (uint32_t)(r * LDP + c * 4) * 4,
              A + (size_t)(m0 + r) * DMODEL + kt * BK + c * 4);
    }
#pragma unroll
    for (int p = 0; p < 4; p++) {
        int i = tid + p * 256;
        int r = i >> 3, c = i & 7;
        cpa16(sB + (uint32_t)(r * LDP + c * 4) * 4,
              W + (size_t)(n0 + r) * DMODEL + kt * BK + c * 4);
    }
}

template <bool SPLIT, bool BIAS>
__global__ void __launch_bounds__(256, 2)
gemm_tc(const float* __restrict__ A,
        const float* __restrict__ W0, const float* __restrict__ W1,
        const float* __restrict__ W2,
        float* __restrict__ C0, float* __restrict__ C1, float* __restrict__ C2,
        const float* __restrict__ bias)
{
    extern __shared__ __align__(16) float smem[];
    const uint32_t sbase = smem_u32(smem);

    const int tid  = threadIdx.x;
    const int wid  = tid >> 5;
    const int lane = tid & 31;
    const int warp_m = wid & 1;       // 0..1
    const int warp_n = wid >> 1;      // 0..3
    const int lr = lane >> 2;         // 0..7
    const int lc = lane & 3;          // 0..3

    const int m0 = blockIdx.y * BM;
    const int n0 = blockIdx.x * BN;
    const int z = blockIdx.z;
    const float* W = (z == 0) ? W0 : (z == 1) ? W1 : W2;
    float* C = (z == 0) ? C0 : (z == 1) ? C1 : C2;

    float acc[4][4][4];
#pragma unroll
    for (int mi = 0; mi < 4; mi++)
#pragma unroll
        for (int ni = 0; ni < 4; ni++)
#pragma unroll
            for (int k = 0; k < 4; k++) acc[mi][ni][k] = 0.0f;

    // Prefill pipeline
#pragma unroll
    for (int s = 0; s < STAGES; s++) {
        uint32_t sA = sbase + (uint32_t)(s * STAGE_FLOATS) * 4;
        load_stage(A, W, m0, n0, s, sA, sA + 128 * LDP * 4, tid);
        cpa_commit();
    }

    const float* Asw = smem;                      // stage base views
    for (int kt = 0; kt < NKT; kt++) {
        const int s = kt % STAGES;
        const float* As = Asw + (size_t)s * STAGE_FLOATS;
        const float* Bs = As + 128 * LDP;

        cpa_wait2();
        __syncthreads();

#pragma unroll
        for (int ks = 0; ks < 4; ks++) {
            uint32_t a[4][4], b[4][2];
#pragma unroll
            for (int mi = 0; mi < 4; mi++) {
                const int m = warp_m * 64 + mi * 16;
                const int k = ks * 8 + lc;
                a[mi][0] = __float_as_uint(As[(m + lr) * LDP + k]);
                a[mi][1] = __float_as_uint(As[(m + lr + 8) * LDP + k]);
                a[mi][2] = __float_as_uint(As[(m + lr) * LDP + k + 4]);
                a[mi][3] = __float_as_uint(As[(m + lr + 8) * LDP + k + 4]);
            }
#pragma unroll
            for (int ni = 0; ni < 4; ni++) {
                const int n = warp_n * 32 + ni * 8;
                const int k = ks * 8 + lc;
                b[ni][0] = __float_as_uint(Bs[(n + lr) * LDP + k]);
                b[ni][1] = __float_as_uint(Bs[(n + lr) * LDP + k + 4]);
            }
#pragma unroll
            for (int mi = 0; mi < 4; mi++)
#pragma unroll
                for (int ni = 0; ni < 4; ni++)
                    mma_tf32(acc[mi][ni], a[mi], b[ni]);
        }

        __syncthreads();
        if (kt + STAGES < NKT) {
            uint32_t sA = sbase + (uint32_t)(s * STAGE_FLOATS) * 4;
            load_stage(A, W, m0, n0, kt + STAGES, sA, sA + 128 * LDP * 4, tid);
        }
        cpa_commit();
    }

    // Epilogue
#pragma unroll
    for (int mi = 0; mi < 4; mi++) {
#pragma unroll
        for (int ni = 0; ni < 4; ni++) {
            const int n = n0 + warp_n * 32 + ni * 8 + lc * 2;
#pragma unroll
            for (int half = 0; half < 2; half++) {
                const int mg = m0 + warp_m * 64 + mi * 16 + lr + half * 8;
                float v0 = acc[mi][ni][half * 2 + 0];
                float v1 = acc[mi][ni][half * 2 + 1];
                if (BIAS) { v0 += bias[n]; v1 += bias[n + 1]; }
                float* dst;
                if (SPLIT) {
                    const int bb = mg >> 11;
                    const int t  = mg & (T_SEQ - 1);
                    const int h  = n >> 6;
                    const int d0 = n & 63;
                    dst = C + (((size_t)(bb * NH + h) * T_SEQ + t) * HD + d0);
                } else {
                    dst = C + (size_t)mg * DMODEL + n;
                }
                *(float2*)dst = make_float2(v0, v1);
            }
        }
    }
}

// ---------------------------------------------------------------------------
// tf32 RN pre-rounding (removes truncation bias)
// ---------------------------------------------------------------------------
__global__ void __launch_bounds__(256)
round_tf32(const float4* __restrict__ in, float4* __restrict__ out, int n4)
{
    int i = blockIdx.x * blockDim.x + threadIdx.x;
    if (i < n4) {
        float4 v = in[i];
        v.x = rtf32(v.x); v.y = rtf32(v.y); v.z = rtf32(v.z); v.w = rtf32(v.w);
        out[i] = v;
    }
}

// ---------------------------------------------------------------------------
// Flash attention (causal), fp32 — unchanged from R1 (passed, rel_err 7e-7)
// ---------------------------------------------------------------------------
#define KS_LD 68

extern __shared__ float fa_smem[];

__global__ void __launch_bounds__(256)
flash_attn(const float* __restrict__ Q, const float* __restrict__ Kg,
           const float* __restrict__ Vg, float* __restrict__ ctx)
{
    const int qt = blockIdx.x;
    const int h  = blockIdx.y;
    const int b  = blockIdx.z;
    const int i0 = qt * 64;
    const size_t hb = ((size_t)(b * NH + h)) * T_SEQ * HD;

    float* Qs = fa_smem;
    float* Ks = Qs + 64 * 64;
    float* Vs = Ks + 64 * KS_LD;
    float* Ps = Vs + 64 * 64;

    const int tid  = threadIdx.x;
    const int wid  = tid >> 5;
    const int lane = tid & 31;

#pragma unroll
    for (int p = 0; p < 4; p++) {
        int idx = p * 1024 + tid * 4;
        int row = idx >> 6, col = idx & 63;
        *(float4*)&Qs[row * 64 + col] =
            *(const float4*)&Q[hb + (size_t)(i0 + row) * HD + col];
    }

    float m_run[8], l_run[8], o0[8], o1[8];
#pragma unroll
    for (int r = 0; r < 8; r++) {
        m_run[r] = -1e30f; l_run[r] = 0.0f; o0[r] = 0.0f; o1[r] = 0.0f;
    }

    const int qbase = i0 + wid * 8;

    for (int jt = 0; jt <= qt; jt++) {
        const int j0 = jt * 64;
        __syncthreads();
#pragma unroll
        for (int p = 0; p < 4; p++) {
            int idx = p * 1024 + tid * 4;
            int row = idx >> 6, col = idx & 63;
            *(float4*)&Ks[row * KS_LD + col] =
                *(const float4*)&Kg[hb + (size_t)(j0 + row) * HD + col];
            *(float4*)&Vs[row * 64 + col] =
                *(const float4*)&Vg[hb + (size_t)(j0 + row) * HD + col];
        }
        __syncthreads();

        float s0[8], s1[8];
#pragma unroll
        for (int r = 0; r < 8; r++) { s0[r] = 0.0f; s1[r] = 0.0f; }
#pragma unroll
        for (int d = 0; d < 64; d += 4) {
            float4 ka = *(float4*)&Ks[lane * KS_LD + d];
            float4 kb = *(float4*)&Ks[(lane + 32) * KS_LD + d];
#pragma unroll
            for (int r = 0; r < 8; r++) {
                float4 qv = *(float4*)&Qs[(wid * 8 + r) * 64 + d];
                s0[r] += qv.x * ka.x + qv.y * ka.y + qv.z * ka.z + qv.w * ka.w;
                s1[r] += qv.x * kb.x + qv.y * kb.y + qv.z * kb.z + qv.w * kb.w;
            }
        }

        const bool diag = (jt == qt);
#pragma unroll
        for (int r = 0; r < 8; r++) {
            const int qi = qbase + r;
            float v0 = s0[r] * 0.125f;
            float v1 = s1[r] * 0.125f;
            if (diag) {
                if (j0 + lane > qi)       v0 = -1e30f;
                if (j0 + lane + 32 > qi)  v1 = -1e30f;
            }
            float mx = fmaxf(v0, v1);
#pragma unroll
            for (int off = 16; off; off >>= 1)
                mx = fmaxf(mx, __shfl_xor_sync(0xffffffffu, mx, off));
            const float m_new = fmaxf(m_run[r], mx);
            const float alpha = __expf(m_run[r] - m_new);
            const float p0 = __expf(v0 - m_new);
            const float p1 = __expf(v1 - m_new);
            float sum = p0 + p1;
#pragma unroll
            for (int off = 16; off; off >>= 1)
                sum += __shfl_xor_sync(0xffffffffu, sum, off);
            l_run[r] = l_run[r] * alpha + sum;
            m_run[r] = m_new;
            o0[r] *= alpha; o1[r] *= alpha;
            Ps[(wid * 8 + r) * 64 + lane]      = p0;
            Ps[(wid * 8 + r) * 64 + lane + 32] = p1;
        }
        __syncwarp();

#pragma unroll
        for (int c = 0; c < 64; c += 4) {
            float va0 = Vs[(c + 0) * 64 + lane];
            float va1 = Vs[(c + 1) * 64 + lane];
            float va2 = Vs[(c + 2) * 64 + lane];
            float va3 = Vs[(c + 3) * 64 + lane];
            float vb0 = Vs[(c + 0) * 64 + lane + 32];
            float vb1 = Vs[(c + 1) * 64 + lane + 32];
            float vb2 = Vs[(c + 2) * 64 + lane + 32];
            float vb3 = Vs[(c + 3) * 64 + lane + 32];
#pragma unroll
            for (int r = 0; r < 8; r++) {
                float4 p4 = *(float4*)&Ps[(wid * 8 + r) * 64 + c];
                o0[r] += p4.x * va0 + p4.y * va1 + p4.z * va2 + p4.w * va3;
                o1[r] += p4.x * vb0 + p4.y * vb1 + p4.z * vb2 + p4.w * vb3;
            }
        }
    }

#pragma unroll
    for (int r = 0; r < 8; r++) {
        const float inv = 1.0f / l_run[r];
        float* dst = ctx + (size_t)(b * T_SEQ + i0 + wid * 8 + r) * DMODEL + h * HD;
        dst[lane]      = rtf32(o0[r] * inv);     // pre-round for tf32 O-proj
        dst[lane + 32] = rtf32(o1[r] * inv);
    }
}

// ---------------------------------------------------------------------------

extern "C" void kernel_launch(void* const* d_in, const int* in_sizes, int n_in,
                              void* d_out, int out_size)
{
    const float* x  = (const float*)d_in[0];
    const float* wq = (const float*)d_in[1];
    const float* wk = (const float*)d_in[2];
    const float* wv = (const float*)d_in[3];
    const float* wo = (const float*)d_in[4];
    const float* bo = (const float*)d_in[5];
    float* out = (float*)d_out;

    float *pQ, *pK, *pV, *pCtx, *pXr, *pWr;
    cudaGetSymbolAddress((void**)&pQ, g_Q);
    cudaGetSymbolAddress((void**)&pK, g_K);
    cudaGetSymbolAddress((void**)&pV, g_V);
    cudaGetSymbolAddress((void**)&pCtx, g_ctx);
    cudaGetSymbolAddress((void**)&pXr, g_xr);
    cudaGetSymbolAddress((void**)&pWr, g_wr);

    float* pWq = pWr;
    float* pWk = pWr + (size_t)DMODEL * DMODEL;
    float* pWv = pWr + 2 * (size_t)DMODEL * DMODEL;
    float* pWo = pWr + 3 * (size_t)DMODEL * DMODEL;

    cudaFuncSetAttribute(gemm_tc<true, false>,
                         cudaFuncAttributeMaxDynamicSharedMemorySize, GEMM_SMEM);
    cudaFuncSetAttribute(gemm_tc<false, true>,
                         cudaFuncAttributeMaxDynamicSharedMemorySize, GEMM_SMEM);
    const int fa_smem_bytes =
        (64 * 64 + 64 * KS_LD + 64 * 64 + 64 * 64) * (int)sizeof(float);
    cudaFuncSetAttribute(flash_attn, cudaFuncAttributeMaxDynamicSharedMemorySize,
                         fa_smem_bytes);

    // 1) tf32 RN pre-rounding
    {
        int n4 = (M_ROWS * DMODEL) / 4;
        round_tf32<<<n4 / 256, 256>>>((const float4*)x, (float4*)pXr, n4);
        int w4 = (DMODEL * DMODEL) / 4;
        round_tf32<<<w4 / 256, 256>>>((const float4*)wq, (float4*)pWq, w4);
        round_tf32<<<w4 / 256, 256>>>((const float4*)wk, (float4*)pWk, w4);
        round_tf32<<<w4 / 256, 256>>>((const float4*)wv, (float4*)pWv, w4);
        round_tf32<<<w4 / 256, 256>>>((const float4*)wo, (float4*)pWo, w4);
    }

    // 2) fused QKV projections (tf32 tensor cores), split-head outputs
    {
        dim3 grid(DMODEL / BN, M_ROWS / BM, 3);
        gemm_tc<true, false><<<grid, 256, GEMM_SMEM>>>(
            pXr, pWq, pWk, pWv, pQ, pK, pV, nullptr);
    }

    // 3) attention (fp32)
    {
        dim3 fgrid(T_SEQ / 64, NH, BATCH_N);
        flash_attn<<<fgrid, 256, fa_smem_bytes>>>(pQ, pK, pV, pCtx);
    }

    // 4) output projection + bias
    {
        dim3 grid(DMODEL / BN, M_ROWS / BM, 1);
        gemm_tc<false, true><<<grid, 256, GEMM_SMEM>>>(
            pCtx, pWo, pWo, pWo, out, out, out, bo);
    }
}

// round 4
// speedup vs baseline: 3.9341x; 2.2097x over previous
#include <cuda_runtime.h>
#include <cuda_fp16.h>
#include <cstdint>
#include <cstddef>

// Problem constants
#define BATCH_N 4
#define T_SEQ   2048
#define NH      16
#define HD      64
#define DMODEL  1024
#define M_ROWS  (BATCH_N * T_SEQ)   // 8192

// GEMM tiling (mma.sync m16n8k8 tf32)
#define BM 128
#define BN 128
#define BK 32
#define STAGES 3
#define NKT (DMODEL / BK)        // 32
#define LDP 36
#define STAGE_FLOATS (2 * 128 * LDP)
#define GEMM_SMEM (STAGES * STAGE_FLOATS * 4)

// Flash-attention smem layout (bytes)
#define FA_QS    0
#define FA_KS0   17408
#define FA_KS1   34816
#define FA_VS0   52224
#define FA_VS1   61440
#define FA_SMEM  70656

// Scratch
__device__ float  g_Q[(size_t)BATCH_N * NH * T_SEQ * HD];
__device__ float  g_K[(size_t)BATCH_N * NH * T_SEQ * HD];
__device__ __half g_Vt[(size_t)BATCH_N * NH * HD * T_SEQ];  // [B,H,hd,T] fp16
__device__ float  g_ctx[(size_t)M_ROWS * DMODEL];
__device__ float  g_xr[(size_t)M_ROWS * DMODEL];
__device__ float  g_wr[4][(size_t)DMODEL * DMODEL];

// ---------------------------------------------------------------------------
// Helpers
// ---------------------------------------------------------------------------
__device__ __forceinline__ uint32_t smem_u32(const void* p) {
    uint32_t a;
    asm("{ .reg .u64 t; cvta.to.shared.u64 t, %1; cvt.u32.u64 %0, t; }"
        : "=r"(a) : "l"(p));
    return a;
}
__device__ __forceinline__ float rtf32(float x) {
    uint32_t u;
    asm("cvt.rna.tf32.f32 %0, %1;" : "=r"(u) : "f"(x));
    return __uint_as_float(u);
}
__device__ __forceinline__ float ex2(float x) {
    float y;
    asm("ex2.approx.f32 %0, %1;" : "=f"(y) : "f"(x));
    return y;
}
__device__ __forceinline__ void cpa16(uint32_t s, const void* g) {
    asm volatile("cp.async.cg.shared.global [%0], [%1], 16;" :: "r"(s), "l"(g));
}
__device__ __forceinline__ void cpa_commit() {
    asm volatile("cp.async.commit_group;");
}
__device__ __forceinline__ void mma_tf32(float* d, const uint32_t* a,
                                         const uint32_t* b) {
    asm volatile(
        "mma.sync.aligned.m16n8k8.row.col.f32.tf32.tf32.f32 "
        "{%0,%1,%2,%3}, {%4,%5,%6,%7}, {%8,%9}, {%0,%1,%2,%3};"
        : "+f"(d[0]), "+f"(d[1]), "+f"(d[2]), "+f"(d[3])
        : "r"(a[0]), "r"(a[1]), "r"(a[2]), "r"(a[3]), "r"(b[0]), "r"(b[1]));
}
__device__ __forceinline__ void mma_f16(float* d, const uint32_t* a,
                                        const uint32_t* b) {
    asm volatile(
        "mma.sync.aligned.m16n8k16.row.col.f32.f16.f16.f32 "
        "{%0,%1,%2,%3}, {%4,%5,%6,%7}, {%8,%9}, {%0,%1,%2,%3};"
        : "+f"(d[0]), "+f"(d[1]), "+f"(d[2]), "+f"(d[3])
        : "r"(a[0]), "r"(a[1]), "r"(a[2]), "r"(a[3]), "r"(b[0]), "r"(b[1]));
}

// ---------------------------------------------------------------------------
// tf32 tensor-core GEMM: C = A @ W^T (+bias). (unchanged core from R3)
// SPLIT epilogue: z<2 -> tf32-rounded [B,H,T,hd]; z==2 -> fp16 transposed
// [B,H,hd,T] for the attention PV operand.
// ---------------------------------------------------------------------------
__device__ __forceinline__ void load_stage(const float* __restrict__ A,
                                           const float* __restrict__ W,
                                           int m0, int n0, int kt,
                                           uint32_t sA, uint32_t sB, int tid)
{
#pragma unroll
    for (int p = 0; p < 4; p++) {
        int i = tid + p * 256;
        int r = i >> 3, c = i & 7;
        cpa16(sA + (uint32_t)(r * LDP + c * 4) * 4,
              A + (size_t)(m0 + r) * DMODEL + kt * BK + c * 4);
    }
#pragma unroll
    for (int p = 0; p < 4; p++) {
        int i = tid + p * 256;
        int r = i >> 3, c = i & 7;
        cpa16(sB + (uint32_t)(r * LDP + c * 4) * 4,
              W + (size_t)(n0 + r) * DMODEL + kt * BK + c * 4);
    }
}

template <bool SPLIT, bool BIAS>
__global__ void __launch_bounds__(256, 2)
gemm_tc(const float* __restrict__ A,
        const float* __restrict__ W0, const float* __restrict__ W1,
        const float* __restrict__ W2,
        float* __restrict__ C0, float* __restrict__ C1, float* __restrict__ C2,
        const float* __restrict__ bias)
{
    extern __shared__ __align__(16) float smem[];
    const uint32_t sbase = smem_u32(smem);

    const int tid  = threadIdx.x;
    const int wid  = tid >> 5;
    const int lane = tid & 31;
    const int warp_m = wid & 1;
    const int warp_n = wid >> 1;
    const int lr = lane >> 2;
    const int lc = lane & 3;

    const int m0 = blockIdx.y * BM;
    const int n0 = blockIdx.x * BN;
    const int z = blockIdx.z;
    const float* W = (z == 0) ? W0 : (z == 1) ? W1 : W2;
    float* C = (z == 0) ? C0 : (z == 1) ? C1 : C2;

    float acc[4][4][4];
#pragma unroll
    for (int mi = 0; mi < 4; mi++)
#pragma unroll
        for (int ni = 0; ni < 4; ni++)
#pragma unroll
            for (int k = 0; k < 4; k++) acc[mi][ni][k] = 0.0f;

#pragma unroll
    for (int s = 0; s < STAGES; s++) {
        uint32_t sA = sbase + (uint32_t)(s * STAGE_FLOATS) * 4;
        load_stage(A, W, m0, n0, s, sA, sA + 128 * LDP * 4, tid);
        cpa_commit();
    }

    for (int kt = 0; kt < NKT; kt++) {
        const int s = kt % STAGES;
        const float* As = smem + (size_t)s * STAGE_FLOATS;
        const float* Bs = As + 128 * LDP;

        asm volatile("cp.async.wait_group 2;");
        __syncthreads();

#pragma unroll
        for (int ks = 0; ks < 4; ks++) {
            uint32_t a[4][4], b[4][2];
#pragma unroll
            for (int mi = 0; mi < 4; mi++) {
                const int m = warp_m * 64 + mi * 16;
                const int k = ks * 8 + lc;
                a[mi][0] = __float_as_uint(As[(m + lr) * LDP + k]);
                a[mi][1] = __float_as_uint(As[(m + lr + 8) * LDP + k]);
                a[mi][2] = __float_as_uint(As[(m + lr) * LDP + k + 4]);
                a[mi][3] = __float_as_uint(As[(m + lr + 8) * LDP + k + 4]);
            }
#pragma unroll
            for (int ni = 0; ni < 4; ni++) {
                const int n = warp_n * 32 + ni * 8;
                const int k = ks * 8 + lc;
                b[ni][0] = __float_as_uint(Bs[(n + lr) * LDP + k]);
                b[ni][1] = __float_as_uint(Bs[(n + lr) * LDP + k + 4]);
            }
#pragma unroll
            for (int mi = 0; mi < 4; mi++)
#pragma unroll
                for (int ni = 0; ni < 4; ni++)
                    mma_tf32(acc[mi][ni], a[mi], b[ni]);
        }

        __syncthreads();
        if (kt + STAGES < NKT) {
            uint32_t sA = sbase + (uint32_t)(s * STAGE_FLOATS) * 4;
            load_stage(A, W, m0, n0, kt + STAGES, sA, sA + 128 * LDP * 4, tid);
        }
        cpa_commit();
    }

#pragma unroll
    for (int mi = 0; mi < 4; mi++) {
#pragma unroll
        for (int ni = 0; ni < 4; ni++) {
            const int n = n0 + warp_n * 32 + ni * 8 + lc * 2;
#pragma unroll
            for (int half_i = 0; half_i < 2; half_i++) {
                const int mg = m0 + warp_m * 64 + mi * 16 + lr + half_i * 8;
                float v0 = acc[mi][ni][half_i * 2 + 0];
                float v1 = acc[mi][ni][half_i * 2 + 1];
                if (BIAS) { v0 += bias[n]; v1 += bias[n + 1]; }
                if (SPLIT) {
                    const int bb = mg >> 11;
                    const int t  = mg & (T_SEQ - 1);
                    const int hh = n >> 6;
                    const int d0 = n & 63;
                    if (z == 2) {   // V: fp16, transposed [B,H,hd,T]
                        __half* Vt = (__half*)C;
                        size_t idx = (((size_t)(bb * NH + hh)) * HD + d0)
                                     * T_SEQ + t;
                        Vt[idx]         = __float2half_rn(v0);
                        Vt[idx + T_SEQ] = __float2half_rn(v1);
                    } else {        // Q/K: tf32-rounded for bias-free S mma
                        float* dst = C + (((size_t)(bb * NH + hh) * T_SEQ + t)
                                          * HD + d0);
                        *(float2*)dst = make_float2(rtf32(v0), rtf32(v1));
                    }
                } else {
                    float* dst = C + (size_t)mg * DMODEL + n;
                    *(float2*)dst = make_float2(v0, v1);
                }
            }
        }
    }
}

// ---------------------------------------------------------------------------
// tf32 RN pre-rounding
// ---------------------------------------------------------------------------
__global__ void __launch_bounds__(256)
round_tf32(const float4* __restrict__ in, float4* __restrict__ out, int n4)
{
    int i = blockIdx.x * blockDim.x + threadIdx.x;
    if (i < n4) {
        float4 v = in[i];
        v.x = rtf32(v.x); v.y = rtf32(v.y); v.z = rtf32(v.z); v.w = rtf32(v.w);
        out[i] = v;
    }
}

// ---------------------------------------------------------------------------
// Tensor-core flash attention (causal).
// CTA = 64 q-rows, 4 warps (16 rows each). S via tf32 mma from Qs/Ks smem;
// softmax in exp2 domain; P packed to fp16 A-frags directly from accumulators;
// PV via m16n8k16 fp16 with V pre-transposed [hd][T] fp16 in gmem.
// Double-buffered cp.async K/V tiles. Heavy (large qt) CTAs launch first.
// ---------------------------------------------------------------------------
__device__ __forceinline__ void fa_load_kv(const float* __restrict__ Kg,
                                           const __half* __restrict__ Vtg,
                                           uint32_t ks, uint32_t vs,
                                           size_t hb, size_t vb, int j0, int tid)
{
#pragma unroll
    for (int p = 0; p < 8; p++) {           // K tile: 64 rows x 64 f32
        int i = p * 128 + tid;
        int r = i >> 4, c = i & 15;
        cpa16(ks + (uint32_t)(r * 272 + c * 16),
              (const char*)(Kg + hb + (size_t)(j0 + r) * HD) + c * 16);
    }
#pragma unroll
    for (int p = 0; p < 4; p++) {           // V tile: 64 d-rows x 64 keys fp16
        int i = p * 128 + tid;
        int d = i >> 3, c = i & 7;
        cpa16(vs + (uint32_t)(d * 144 + c * 16),
              (const char*)(Vtg + vb + (size_t)d * T_SEQ + j0) + c * 16);
    }
}

__global__ void __launch_bounds__(128, 2)
flash_attn_tc(const float* __restrict__ Qg, const float* __restrict__ Kg,
              const __half* __restrict__ Vtg, float* __restrict__ ctx)
{
    extern __shared__ __align__(16) char sm[];
    float*  Qs  = (float*)(sm + FA_QS);      // [64][68] f32
    float*  KsA[2] = { (float*)(sm + FA_KS0), (float*)(sm + FA_KS1) };
    __half* VsA[2] = { (__half*)(sm + FA_VS0), (__half*)(sm + FA_VS1) };

    const int qt = (T_SEQ / 64 - 1) - blockIdx.x;   // heavy first
    const int h  = blockIdx.y;
    const int b  = blockIdx.z;
    const int i0 = qt * 64;
    const size_t hb = ((size_t)(b * NH + h)) * T_SEQ * HD;
    const size_t vb = ((size_t)(b * NH + h)) * HD * T_SEQ;

    const int tid  = threadIdx.x;
    const int wid  = tid >> 5;
    const int lane = tid & 31;
    const int lr = lane >> 2;
    const int lc = lane & 3;

    // Prologue: Q tile + KV tile 0 (one cp.async group)
    {
        const uint32_t qs = smem_u32(Qs);
#pragma unroll
        for (int p = 0; p < 8; p++) {
            int i = p * 128 + tid;
            int r = i >> 4, c = i & 15;
            cpa16(qs + (uint32_t)(r * 272 + c * 16),
                  (const char*)(Qg + hb + (size_t)(i0 + r) * HD) + c * 16);
        }
        fa_load_kv(Kg, Vtg, smem_u32(KsA[0]), smem_u32(VsA[0]), hb, vb, 0, tid);
        cpa_commit();
    }

    float m0 = -1e30f, m1 = -1e30f, l0 = 0.0f, l1 = 0.0f;
    float o[8][4];
#pragma unroll
    for (int nf = 0; nf < 8; nf++)
#pragma unroll
        for (int j = 0; j < 4; j++) o[nf][j] = 0.0f;

    const int qr = wid * 16 + lr;           // in-tile query row (low)
    const float kk = 0.18033688011112042f;  // log2(e) / sqrt(64)

    for (int jt = 0; jt <= qt; jt++) {
        if (jt < qt) {
            const int nb = (jt + 1) & 1;
            fa_load_kv(Kg, Vtg, smem_u32(KsA[nb]), smem_u32(VsA[nb]),
                       hb, vb, (jt + 1) * 64, tid);
        }
        cpa_commit();
        asm volatile("cp.async.wait_group 1;");
        __syncthreads();

        const float*  Ks = KsA[jt & 1];
        const __half* Vs = VsA[jt & 1];

        // ---- S = Q @ K^T (tf32 mma) ----
        float s[8][4];
#pragma unroll
        for (int nf = 0; nf < 8; nf++)
#pragma unroll
            for (int j = 0; j < 4; j++) s[nf][j] = 0.0f;

#pragma unroll
        for (int kc = 0; kc < 8; kc++) {
            uint32_t a[4];
            a[0] = __float_as_uint(Qs[qr * 68 + kc * 8 + lc]);
            a[1] = __float_as_uint(Qs[(qr + 8) * 68 + kc * 8 + lc]);
            a[2] = __float_as_uint(Qs[qr * 68 + kc * 8 + lc + 4]);
            a[3] = __float_as_uint(Qs[(qr + 8) * 68 + kc * 8 + lc + 4]);
#pragma unroll
            for (int nf = 0; nf < 8; nf++) {
                uint32_t bf[2];
                bf[0] = __float_as_uint(Ks[(nf * 8 + lr) * 68 + kc * 8 + lc]);
                bf[1] = __float_as_uint(Ks[(nf * 8 + lr) * 68 + kc * 8 + lc + 4]);
                mma_tf32(s[nf], a, bf);
            }
        }

        // ---- online softmax (exp2 domain) ----
        const bool diag = (jt == qt);
        float mx0 = -1e30f, mx1 = -1e30f;
#pragma unroll
        for (int nf = 0; nf < 8; nf++) {
            float e0 = s[nf][0] * kk, e1 = s[nf][1] * kk;
            float e2 = s[nf][2] * kk, e3 = s[nf][3] * kk;
            if (diag) {
                const int c0 = nf * 8 + lc * 2, c1 = c0 + 1;
                if (c0 > qr)     e0 = -1e30f;
                if (c1 > qr)     e1 = -1e30f;
                if (c0 > qr + 8) e2 = -1e30f;
                if (c1 > qr + 8) e3 = -1e30f;
            }
            s[nf][0] = e0; s[nf][1] = e1; s[nf][2] = e2; s[nf][3] = e3;
            mx0 = fmaxf(mx0, fmaxf(e0, e1));
            mx1 = fmaxf(mx1, fmaxf(e2, e3));
        }
        mx0 = fmaxf(mx0, __shfl_xor_sync(0xffffffffu, mx0, 1));
        mx0 = fmaxf(mx0, __shfl_xor_sync(0xffffffffu, mx0, 2));
        mx1 = fmaxf(mx1, __shfl_xor_sync(0xffffffffu, mx1, 1));
        mx1 = fmaxf(mx1, __shfl_xor_sync(0xffffffffu, mx1, 2));

        const float mn0 = fmaxf(m0, mx0), mn1 = fmaxf(m1, mx1);
        const float al0 = ex2(m0 - mn0),  al1 = ex2(m1 - mn1);

        uint32_t ph[8][2];
        float sum0 = 0.0f, sum1 = 0.0f;
#pragma unroll
        for (int nf = 0; nf < 8; nf++) {
            float p0 = ex2(s[nf][0] - mn0), p1 = ex2(s[nf][1] - mn0);
            float p2 = ex2(s[nf][2] - mn1), p3 = ex2(s[nf][3] - mn1);
            sum0 += p0 + p1;
            sum1 += p2 + p3;
            __half2 hlo = __floats2half2_rn(p0, p1);
            __half2 hhi = __floats2half2_rn(p2, p3);
            ph[nf][0] = *(uint32_t*)&hlo;
            ph[nf][1] = *(uint32_t*)&hhi;
        }
        sum0 += __shfl_xor_sync(0xffffffffu, sum0, 1);
        sum0 += __shfl_xor_sync(0xffffffffu, sum0, 2);
        sum1 += __shfl_xor_sync(0xffffffffu, sum1, 1);
        sum1 += __shfl_xor_sync(0xffffffffu, sum1, 2);
        l0 = l0 * al0 + sum0;
        l1 = l1 * al1 + sum1;
        m0 = mn0; m1 = mn1;
#pragma unroll
        for (int nf = 0; nf < 8; nf++) {
            o[nf][0] *= al0; o[nf][1] *= al0;
            o[nf][2] *= al1; o[nf][3] *= al1;
        }

        // ---- O += P @ V (fp16 mma, P packed from accumulators) ----
#pragma unroll
        for (int kc = 0; kc < 4; kc++) {
            uint32_t a[4] = { ph[2 * kc][0], ph[2 * kc][1],
                              ph[2 * kc + 1][0], ph[2 * kc + 1][1] };
#pragma unroll
            for (int nf = 0; nf < 8; nf++) {
                const __half* vp = Vs + (nf * 8 + lr) * 72 + kc * 16 + lc * 2;
                uint32_t bf[2];
                bf[0] = *(const uint32_t*)vp;
                bf[1] = *(const uint32_t*)(vp + 8);
                mma_f16(o[nf], a, bf);
            }
        }
        __syncthreads();   // protect buffers before next prefetch overwrites
    }

    // ---- epilogue: normalize, tf32-round, write ctx [B*T, DMODEL] ----
    const float inv0 = 1.0f / l0, inv1 = 1.0f / l1;
    const int t_lo = i0 + qr;
#pragma unroll
    for (int nf = 0; nf < 8; nf++) {
        const int d = nf * 8 + lc * 2;
        float* p0 = ctx + ((size_t)(b * T_SEQ + t_lo)) * DMODEL + h * HD + d;
        *(float2*)p0 = make_float2(rtf32(o[nf][0] * inv0),
                                   rtf32(o[nf][1] * inv0));
        float* p1 = p0 + (size_t)8 * DMODEL;
        *(float2*)p1 = make_float2(rtf32(o[nf][2] * inv1),
                                   rtf32(o[nf][3] * inv1));
    }
}

// ---------------------------------------------------------------------------

extern "C" void kernel_launch(void* const* d_in, const int* in_sizes, int n_in,
                              void* d_out, int out_size)
{
    const float* x  = (const float*)d_in[0];
    const float* wq = (const float*)d_in[1];
    const float* wk = (const float*)d_in[2];
    const float* wv = (const float*)d_in[3];
    const float* wo = (const float*)d_in[4];
    const float* bo = (const float*)d_in[5];
    float* out = (float*)d_out;

    float *pQ, *pK, *pCtx, *pXr, *pWr;
    __half* pVt;
    cudaGetSymbolAddress((void**)&pQ, g_Q);
    cudaGetSymbolAddress((void**)&pK, g_K);
    cudaGetSymbolAddress((void**)&pVt, g_Vt);
    cudaGetSymbolAddress((void**)&pCtx, g_ctx);
    cudaGetSymbolAddress((void**)&pXr, g_xr);
    cudaGetSymbolAddress((void**)&pWr, g_wr);

    float* pWq = pWr;
    float* pWk = pWr + (size_t)DMODEL * DMODEL;
    float* pWv = pWr + 2 * (size_t)DMODEL * DMODEL;
    float* pWo = pWr + 3 * (size_t)DMODEL * DMODEL;

    cudaFuncSetAttribute(gemm_tc<true, false>,
                         cudaFuncAttributeMaxDynamicSharedMemorySize, GEMM_SMEM);
    cudaFuncSetAttribute(gemm_tc<false, true>,
                         cudaFuncAttributeMaxDynamicSharedMemorySize, GEMM_SMEM);
    cudaFuncSetAttribute(flash_attn_tc,
                         cudaFuncAttributeMaxDynamicSharedMemorySize, FA_SMEM);

    // 1) tf32 RN pre-rounding of x and weights
    {
        int n4 = (M_ROWS * DMODEL) / 4;
        round_tf32<<<n4 / 256, 256>>>((const float4*)x, (float4*)pXr, n4);
        int w4 = (DMODEL * DMODEL) / 4;
        round_tf32<<<w4 / 256, 256>>>((const float4*)wq, (float4*)pWq, w4);
        round_tf32<<<w4 / 256, 256>>>((const float4*)wk, (float4*)pWk, w4);
        round_tf32<<<w4 / 256, 256>>>((const float4*)wv, (float4*)pWv, w4);
        round_tf32<<<w4 / 256, 256>>>((const float4*)wo, (float4*)pWo, w4);
    }

    // 2) fused QKV projections; Q/K tf32-rounded split-head, V fp16 transposed
    {
        dim3 grid(DMODEL / BN, M_ROWS / BM, 3);
        gemm_tc<true, false><<<grid, 256, GEMM_SMEM>>>(
            pXr, pWq, pWk, pWv, pQ, pK, (float*)pVt, nullptr);
    }

    // 3) tensor-core flash attention
    {
        dim3 fgrid(T_SEQ / 64, NH, BATCH_N);
        flash_attn_tc<<<fgrid, 128, FA_SMEM>>>(pQ, pK, pVt, pCtx);
    }

    // 4) output projection + bias
    {
        dim3 grid(DMODEL / BN, M_ROWS / BM, 1);
        gemm_tc<false, true><<<grid, 256, GEMM_SMEM>>>(
            pCtx, pWo, pWo, pWo, out, out, out, bo);
    }
}

// round 5
// speedup vs baseline: 6.8324x; 1.7367x over previous
#include <cuda_runtime.h>
#include <cuda_fp16.h>
#include <cstdint>
#include <cstddef>

// Problem constants
#define BATCH_N 4
#define T_SEQ   2048
#define NH      16
#define HD      64
#define DMODEL  1024
#define M_ROWS  (BATCH_N * T_SEQ)   // 8192

// GEMM tiling (mma.sync m16n8k16 fp16)
#define BM 128
#define BN 128
#define BK 64
#define STAGES 3
#define NKT (DMODEL / BK)        // 16
#define LDH 72                   // padded leading dim (halves) -> conflict-free
#define STAGE_HALVES (2 * 128 * LDH)
#define GEMM_SMEM (STAGES * STAGE_HALVES * 2)   // 110592 bytes

// Flash-attention smem layout (bytes): all tiles [64][72] halves = 9216 B
#define FA_QS    0
#define FA_KS0   9216
#define FA_KS1   18432
#define FA_VS0   27648
#define FA_VS1   36864
#define FA_SMEM  46080

// Scratch (all fp16 activations)
__device__ __half g_xh [(size_t)M_ROWS * DMODEL];
__device__ __half g_wh [4 * (size_t)DMODEL * DMODEL];   // Wq,Wk,Wv,Wo
__device__ __half g_Qh [(size_t)BATCH_N * NH * T_SEQ * HD];
__device__ __half g_Kh [(size_t)BATCH_N * NH * T_SEQ * HD];
__device__ __half g_Vt [(size_t)BATCH_N * NH * HD * T_SEQ];  // [B,H,hd,T]
__device__ __half g_ctxh[(size_t)M_ROWS * DMODEL];

// ---------------------------------------------------------------------------
// Helpers
// ---------------------------------------------------------------------------
__device__ __forceinline__ uint32_t smem_u32(const void* p) {
    uint32_t a;
    asm("{ .reg .u64 t; cvta.to.shared.u64 t, %1; cvt.u32.u64 %0, t; }"
        : "=r"(a) : "l"(p));
    return a;
}
__device__ __forceinline__ float ex2(float x) {
    float y;
    asm("ex2.approx.f32 %0, %1;" : "=f"(y) : "f"(x));
    return y;
}
__device__ __forceinline__ void cpa16(uint32_t s, const void* g) {
    asm volatile("cp.async.cg.shared.global [%0], [%1], 16;" :: "r"(s), "l"(g));
}
__device__ __forceinline__ void cpa_commit() {
    asm volatile("cp.async.commit_group;");
}
__device__ __forceinline__ void mma_f16(float* d, const uint32_t* a,
                                        const uint32_t* b) {
    asm volatile(
        "mma.sync.aligned.m16n8k16.row.col.f32.f16.f16.f32 "
        "{%0,%1,%2,%3}, {%4,%5,%6,%7}, {%8,%9}, {%0,%1,%2,%3};"
        : "+f"(d[0]), "+f"(d[1]), "+f"(d[2]), "+f"(d[3])
        : "r"(a[0]), "r"(a[1]), "r"(a[2]), "r"(a[3]), "r"(b[0]), "r"(b[1]));
}

// ---------------------------------------------------------------------------
// f32 -> fp16 RN conversion: x + all 4 weights in ONE launch
// ---------------------------------------------------------------------------
#define XN4 ((M_ROWS * DMODEL) / 4)     // 2097152
#define WN4 ((DMODEL * DMODEL) / 4)     // 262144

__global__ void __launch_bounds__(256)
cvt_all(const float4* __restrict__ x,
        const float4* __restrict__ w0, const float4* __restrict__ w1,
        const float4* __restrict__ w2, const float4* __restrict__ w3,
        uint2* __restrict__ xh, uint2* __restrict__ wh)
{
    int i = blockIdx.x * 256 + threadIdx.x;
    const float4* s;
    uint2* d;
    int o;
    if (i < XN4) { s = x; d = xh; o = i; }
    else {
        int j = i - XN4;
        int w = j / WN4;
        o = j - w * WN4;
        s = (w == 0) ? w0 : (w == 1) ? w1 : (w == 2) ? w2 : w3;
        d = wh + (size_t)w * WN4;
    }
    float4 v = s[o];
    __half2 h0 = __floats2half2_rn(v.x, v.y);
    __half2 h1 = __floats2half2_rn(v.z, v.w);
    d[o] = make_uint2(*(uint32_t*)&h0, *(uint32_t*)&h1);
}

// ---------------------------------------------------------------------------
// fp16 tensor-core GEMM: C = A @ W^T (+bias).
// A[M,K] fp16 row-major, W[N,K] fp16 row-major, fp32 accumulate.
// 256 threads, warp grid 2(M) x 4(N), warp tile 64x32, BK=64, 3-stage cp.async.
// SPLIT: z<2 -> fp16 [B,H,T,hd] (Q,K); z==2 -> fp16 transposed [B,H,hd,T] (V).
// ---------------------------------------------------------------------------
__device__ __forceinline__ void load_stage(const __half* __restrict__ A,
                                           const __half* __restrict__ W,
                                           int m0, int n0, int kt,
                                           uint32_t sA, uint32_t sB, int tid)
{
#pragma unroll
    for (int p = 0; p < 4; p++) {           // A: 128 rows x 128B
        int i = tid + p * 256;
        int r = i >> 3, c = i & 7;
        cpa16(sA + (uint32_t)(r * (LDH * 2) + c * 16),
              A + (size_t)(m0 + r) * DMODEL + kt * BK + c * 8);
    }
#pragma unroll
    for (int p = 0; p < 4; p++) {           // B: 128 rows x 128B
        int i = tid + p * 256;
        int r = i >> 3, c = i & 7;
        cpa16(sB + (uint32_t)(r * (LDH * 2) + c * 16),
              W + (size_t)(n0 + r) * DMODEL + kt * BK + c * 8);
    }
}

template <bool SPLIT, bool BIAS>
__global__ void __launch_bounds__(256, 2)
gemm_fp16(const __half* __restrict__ A,
          const __half* __restrict__ W0, const __half* __restrict__ W1,
          const __half* __restrict__ W2,
          void* __restrict__ C0, void* __restrict__ C1, void* __restrict__ C2,
          const float* __restrict__ bias)
{
    extern __shared__ __align__(16) __half smem[];
    const uint32_t sbase = smem_u32(smem);

    const int tid  = threadIdx.x;
    const int wid  = tid >> 5;
    const int lane = tid & 31;
    const int warp_m = wid & 1;
    const int warp_n = wid >> 1;
    const int lr = lane >> 2;
    const int lc = lane & 3;

    const int m0 = blockIdx.y * BM;
    const int n0 = blockIdx.x * BN;
    const int z = blockIdx.z;
    const __half* W = (z == 0) ? W0 : (z == 1) ? W1 : W2;
    void* C = (z == 0) ? C0 : (z == 1) ? C1 : C2;

    float acc[4][4][4];
#pragma unroll
    for (int mi = 0; mi < 4; mi++)
#pragma unroll
        for (int ni = 0; ni < 4; ni++)
#pragma unroll
            for (int k = 0; k < 4; k++) acc[mi][ni][k] = 0.0f;

#pragma unroll
    for (int s = 0; s < STAGES; s++) {
        uint32_t sA = sbase + (uint32_t)(s * STAGE_HALVES) * 2;
        load_stage(A, W, m0, n0, s, sA, sA + 128 * LDH * 2, tid);
        cpa_commit();
    }

    for (int kt = 0; kt < NKT; kt++) {
        const int s = kt % STAGES;
        const __half* As = smem + (size_t)s * STAGE_HALVES;
        const __half* Bs = As + 128 * LDH;

        asm volatile("cp.async.wait_group 2;");
        __syncthreads();

#pragma unroll
        for (int ks = 0; ks < 4; ks++) {       // 4 x k16
            uint32_t a[4][4], b[4][2];
#pragma unroll
            for (int mi = 0; mi < 4; mi++) {
                const int m = warp_m * 64 + mi * 16;
                const int k = ks * 16 + lc * 2;
                a[mi][0] = *(const uint32_t*)&As[(m + lr) * LDH + k];
                a[mi][1] = *(const uint32_t*)&As[(m + lr + 8) * LDH + k];
                a[mi][2] = *(const uint32_t*)&As[(m + lr) * LDH + k + 8];
                a[mi][3] = *(const uint32_t*)&As[(m + lr + 8) * LDH + k + 8];
            }
#pragma unroll
            for (int ni = 0; ni < 4; ni++) {
                const int n = warp_n * 32 + ni * 8;
                const int k = ks * 16 + lc * 2;
                b[ni][0] = *(const uint32_t*)&Bs[(n + lr) * LDH + k];
                b[ni][1] = *(const uint32_t*)&Bs[(n + lr) * LDH + k + 8];
            }
#pragma unroll
            for (int mi = 0; mi < 4; mi++)
#pragma unroll
                for (int ni = 0; ni < 4; ni++)
                    mma_f16(acc[mi][ni], a[mi], b[ni]);
        }

        __syncthreads();
        if (kt + STAGES < NKT) {
            uint32_t sA = sbase + (uint32_t)(s * STAGE_HALVES) * 2;
            load_stage(A, W, m0, n0, kt + STAGES, sA, sA + 128 * LDH * 2, tid);
        }
        cpa_commit();
    }

#pragma unroll
    for (int mi = 0; mi < 4; mi++) {
#pragma unroll
        for (int ni = 0; ni < 4; ni++) {
            const int n = n0 + warp_n * 32 + ni * 8 + lc * 2;
#pragma unroll
            for (int half_i = 0; half_i < 2; half_i++) {
                const int mg = m0 + warp_m * 64 + mi * 16 + lr + half_i * 8;
                float v0 = acc[mi][ni][half_i * 2 + 0];
                float v1 = acc[mi][ni][half_i * 2 + 1];
                if (SPLIT) {
                    const int bb = mg >> 11;
                    const int t  = mg & (T_SEQ - 1);
                    const int hh = n >> 6;
                    const int d0 = n & 63;
                    if (z == 2) {   // V: fp16, transposed [B,H,hd,T]
                        __half* Vt = (__half*)C;
                        size_t idx = (((size_t)(bb * NH + hh)) * HD + d0)
                                     * T_SEQ + t;
                        Vt[idx]         = __float2half_rn(v0);
                        Vt[idx + T_SEQ] = __float2half_rn(v1);
                    } else {        // Q/K: fp16 [B,H,T,hd]
                        __half* dst = (__half*)C
                            + (((size_t)(bb * NH + hh) * T_SEQ + t) * HD + d0);
                        *(__half2*)dst = __floats2half2_rn(v0, v1);
                    }
                } else {
                    if (BIAS) { v0 += bias[n]; v1 += bias[n + 1]; }
                    float* dst = (float*)C + (size_t)mg * DMODEL + n;
                    *(float2*)dst = make_float2(v0, v1);
                }
            }
        }
    }
}

// ---------------------------------------------------------------------------
// Tensor-core flash attention (causal), all-fp16 operands, fp32 accum.
// CTA = 64 q-rows, 4 warps. S via fp16 mma; softmax exp2-domain; P packed
// straight from accumulators into fp16 A-frags; PV via fp16 mma with V
// pre-transposed [hd][T]. Double-buffered cp.async K/V.
// ---------------------------------------------------------------------------
__device__ __forceinline__ void fa_load_kv(const __half* __restrict__ Kh,
                                           const __half* __restrict__ Vtg,
                                           uint32_t ks, uint32_t vs,
                                           size_t hb, size_t vb, int j0, int tid)
{
#pragma unroll
    for (int p = 0; p < 4; p++) {           // K tile: 64 rows x 64 halves
        int i = p * 128 + tid;
        int r = i >> 3, c = i & 7;
        cpa16(ks + (uint32_t)(r * 144 + c * 16),
              Kh + hb + (size_t)(j0 + r) * HD + c * 8);
    }
#pragma unroll
    for (int p = 0; p < 4; p++) {           // V tile: 64 d-rows x 64 keys
        int i = p * 128 + tid;
        int d = i >> 3, c = i & 7;
        cpa16(vs + (uint32_t)(d * 144 + c * 16),
              Vtg + vb + (size_t)d * T_SEQ + j0 + c * 8);
    }
}

__global__ void __launch_bounds__(128, 3)
flash_attn_tc(const __half* __restrict__ Qh, const __half* __restrict__ Kh,
              const __half* __restrict__ Vtg, __half* __restrict__ ctx)
{
    extern __shared__ __align__(16) char sm[];
    __half* Qs = (__half*)(sm + FA_QS);                 // [64][72]
    __half* KsA[2] = { (__half*)(sm + FA_KS0), (__half*)(sm + FA_KS1) };
    __half* VsA[2] = { (__half*)(sm + FA_VS0), (__half*)(sm + FA_VS1) };

    const int qt = (T_SEQ / 64 - 1) - blockIdx.x;   // heavy first
    const int h  = blockIdx.y;
    const int b  = blockIdx.z;
    const int i0 = qt * 64;
    const size_t hb = ((size_t)(b * NH + h)) * T_SEQ * HD;
    const size_t vb = ((size_t)(b * NH + h)) * HD * T_SEQ;

    const int tid  = threadIdx.x;
    const int wid  = tid >> 5;
    const int lane = tid & 31;
    const int lr = lane >> 2;
    const int lc = lane & 3;

    // Prologue: Q tile + KV tile 0
    {
        const uint32_t qs = smem_u32(Qs);
#pragma unroll
        for (int p = 0; p < 4; p++) {
            int i = p * 128 + tid;
            int r = i >> 3, c = i & 7;
            cpa16(qs + (uint32_t)(r * 144 + c * 16),
                  Qh + hb + (size_t)(i0 + r) * HD + c * 8);
        }
        fa_load_kv(Kh, Vtg, smem_u32(KsA[0]), smem_u32(VsA[0]), hb, vb, 0, tid);
        cpa_commit();
    }

    float m0 = -1e30f, m1 = -1e30f, l0 = 0.0f, l1 = 0.0f;
    float o[8][4];
#pragma unroll
    for (int nf = 0; nf < 8; nf++)
#pragma unroll
        for (int j = 0; j < 4; j++) o[nf][j] = 0.0f;

    const int qr = wid * 16 + lr;
    const float kk = 0.18033688011112042f;  // log2(e)/sqrt(64)

    for (int jt = 0; jt <= qt; jt++) {
        if (jt < qt) {
            const int nb = (jt + 1) & 1;
            fa_load_kv(Kh, Vtg, smem_u32(KsA[nb]), smem_u32(VsA[nb]),
                       hb, vb, (jt + 1) * 64, tid);
        }
        cpa_commit();
        asm volatile("cp.async.wait_group 1;");
        __syncthreads();

        const __half* Ks = KsA[jt & 1];
        const __half* Vs = VsA[jt & 1];

        // ---- S = Q @ K^T (fp16 mma, k=64 as 4 x k16) ----
        float s[8][4];
#pragma unroll
        for (int nf = 0; nf < 8; nf++)
#pragma unroll
            for (int j = 0; j < 4; j++) s[nf][j] = 0.0f;

#pragma unroll
        for (int kc = 0; kc < 4; kc++) {
            const int k = kc * 16 + lc * 2;
            uint32_t a[4];
            a[0] = *(const uint32_t*)&Qs[qr * 72 + k];
            a[1] = *(const uint32_t*)&Qs[(qr + 8) * 72 + k];
            a[2] = *(const uint32_t*)&Qs[qr * 72 + k + 8];
            a[3] = *(const uint32_t*)&Qs[(qr + 8) * 72 + k + 8];
#pragma unroll
            for (int nf = 0; nf < 8; nf++) {
                uint32_t bf[2];
                bf[0] = *(const uint32_t*)&Ks[(nf * 8 + lr) * 72 + k];
                bf[1] = *(const uint32_t*)&Ks[(nf * 8 + lr) * 72 + k + 8];
                mma_f16(s[nf], a, bf);
            }
        }

        // ---- online softmax (exp2 domain) ----
        const bool diag = (jt == qt);
        float mx0 = -1e30f, mx1 = -1e30f;
#pragma unroll
        for (int nf = 0; nf < 8; nf++) {
            float e0 = s[nf][0] * kk, e1 = s[nf][1] * kk;
            float e2 = s[nf][2] * kk, e3 = s[nf][3] * kk;
            if (diag) {
                const int c0 = nf * 8 + lc * 2, c1 = c0 + 1;
                if (c0 > qr)     e0 = -1e30f;
                if (c1 > qr)     e1 = -1e30f;
                if (c0 > qr + 8) e2 = -1e30f;
                if (c1 > qr + 8) e3 = -1e30f;
            }
            s[nf][0] = e0; s[nf][1] = e1; s[nf][2] = e2; s[nf][3] = e3;
            mx0 = fmaxf(mx0, fmaxf(e0, e1));
            mx1 = fmaxf(mx1, fmaxf(e2, e3));
        }
        mx0 = fmaxf(mx0, __shfl_xor_sync(0xffffffffu, mx0, 1));
        mx0 = fmaxf(mx0, __shfl_xor_sync(0xffffffffu, mx0, 2));
        mx1 = fmaxf(mx1, __shfl_xor_sync(0xffffffffu, mx1, 1));
        mx1 = fmaxf(mx1, __shfl_xor_sync(0xffffffffu, mx1, 2));

        const float mn0 = fmaxf(m0, mx0), mn1 = fmaxf(m1, mx1);
        const float al0 = ex2(m0 - mn0),  al1 = ex2(m1 - mn1);

        uint32_t ph[8][2];
        float sum0 = 0.0f, sum1 = 0.0f;
#pragma unroll
        for (int nf = 0; nf < 8; nf++) {
            float p0 = ex2(s[nf][0] - mn0), p1 = ex2(s[nf][1] - mn0);
            float p2 = ex2(s[nf][2] - mn1), p3 = ex2(s[nf][3] - mn1);
            sum0 += p0 + p1;
            sum1 += p2 + p3;
            __half2 hlo = __floats2half2_rn(p0, p1);
            __half2 hhi = __floats2half2_rn(p2, p3);
            ph[nf][0] = *(uint32_t*)&hlo;
            ph[nf][1] = *(uint32_t*)&hhi;
        }
        sum0 += __shfl_xor_sync(0xffffffffu, sum0, 1);
        sum0 += __shfl_xor_sync(0xffffffffu, sum0, 2);
        sum1 += __shfl_xor_sync(0xffffffffu, sum1, 1);
        sum1 += __shfl_xor_sync(0xffffffffu, sum1, 2);
        l0 = l0 * al0 + sum0;
        l1 = l1 * al1 + sum1;
        m0 = mn0; m1 = mn1;
#pragma unroll
        for (int nf = 0; nf < 8; nf++) {
            o[nf][0] *= al0; o[nf][1] *= al0;
            o[nf][2] *= al1; o[nf][3] *= al1;
        }

        // ---- O += P @ V (fp16 mma) ----
#pragma unroll
        for (int kc = 0; kc < 4; kc++) {
            uint32_t a[4] = { ph[2 * kc][0], ph[2 * kc][1],
                              ph[2 * kc + 1][0], ph[2 * kc + 1][1] };
#pragma unroll
            for (int nf = 0; nf < 8; nf++) {
                const __half* vp = Vs + (nf * 8 + lr) * 72 + kc * 16 + lc * 2;
                uint32_t bf[2];
                bf[0] = *(const uint32_t*)vp;
                bf[1] = *(const uint32_t*)(vp + 8);
                mma_f16(o[nf], a, bf);
            }
        }
        __syncthreads();
    }

    // ---- epilogue: normalize, fp16 ctx [B*T, DMODEL] ----
    const float inv0 = 1.0f / l0, inv1 = 1.0f / l1;
    const int t_lo = i0 + qr;
#pragma unroll
    for (int nf = 0; nf < 8; nf++) {
        const int d = nf * 8 + lc * 2;
        __half* p0 = ctx + ((size_t)(b * T_SEQ + t_lo)) * DMODEL + h * HD + d;
        *(__half2*)p0 = __floats2half2_rn(o[nf][0] * inv0, o[nf][1] * inv0);
        __half* p1 = p0 + (size_t)8 * DMODEL;
        *(__half2*)p1 = __floats2half2_rn(o[nf][2] * inv1, o[nf][3] * inv1);
    }
}

// ---------------------------------------------------------------------------

extern "C" void kernel_launch(void* const* d_in, const int* in_sizes, int n_in,
                              void* d_out, int out_size)
{
    const float* x  = (const float*)d_in[0];
    const float* wq = (const float*)d_in[1];
    const float* wk = (const float*)d_in[2];
    const float* wv = (const float*)d_in[3];
    const float* wo = (const float*)d_in[4];
    const float* bo = (const float*)d_in[5];
    float* out = (float*)d_out;

    __half *pXh, *pWh, *pQh, *pKh, *pVt, *pCtx;
    cudaGetSymbolAddress((void**)&pXh, g_xh);
    cudaGetSymbolAddress((void**)&pWh, g_wh);
    cudaGetSymbolAddress((void**)&pQh, g_Qh);
    cudaGetSymbolAddress((void**)&pKh, g_Kh);
    cudaGetSymbolAddress((void**)&pVt, g_Vt);
    cudaGetSymbolAddress((void**)&pCtx, g_ctxh);

    __half* pWq = pWh;
    __half* pWk = pWh + (size_t)DMODEL * DMODEL;
    __half* pWv = pWh + 2 * (size_t)DMODEL * DMODEL;
    __half* pWo = pWh + 3 * (size_t)DMODEL * DMODEL;

    cudaFuncSetAttribute(gemm_fp16<true, false>,
                         cudaFuncAttributeMaxDynamicSharedMemorySize, GEMM_SMEM);
    cudaFuncSetAttribute(gemm_fp16<false, true>,
                         cudaFuncAttributeMaxDynamicSharedMemorySize, GEMM_SMEM);
    cudaFuncSetAttribute(flash_attn_tc,
                         cudaFuncAttributeMaxDynamicSharedMemorySize, FA_SMEM);

    // 1) single-launch f32->fp16 conversion (x + 4 weights)
    {
        int total = XN4 + 4 * WN4;
        cvt_all<<<total / 256, 256>>>(
            (const float4*)x, (const float4*)wq, (const float4*)wk,
            (const float4*)wv, (const float4*)wo, (uint2*)pXh, (uint2*)pWh);
    }

    // 2) fused QKV projections (fp16 MMA); Q/K split-head, V transposed
    {
        dim3 grid(DMODEL / BN, M_ROWS / BM, 3);
        gemm_fp16<true, false><<<grid, 256, GEMM_SMEM>>>(
            pXh, pWq, pWk, pWv, pQh, pKh, pVt, nullptr);
    }

    // 3) tensor-core flash attention (fp16)
    {
        dim3 fgrid(T_SEQ / 64, NH, BATCH_N);
        flash_attn_tc<<<fgrid, 128, FA_SMEM>>>(pQh, pKh, pVt, pCtx);
    }

    // 4) output projection + bias (fp32 out)
    {
        dim3 grid(DMODEL / BN, M_ROWS / BM, 1);
        gemm_fp16<false, true><<<grid, 256, GEMM_SMEM>>>(
            pCtx, pWo, pWo, pWo, out, out, out, bo);
    }
}

// round 6
// speedup vs baseline: 7.9274x; 1.1603x over previous
#include <cuda_runtime.h>
#include <cuda_fp16.h>
#include <cstdint>
#include <cstddef>

// Problem constants
#define BATCH_N 4
#define T_SEQ   2048
#define NH      16
#define HD      64
#define DMODEL  1024
#define M_ROWS  (BATCH_N * T_SEQ)   // 8192

// GEMM tiling (mma.sync m16n8k16 fp16)
#define BM 128
#define BN 128
#define BK 64
#define STAGES 3
#define NKT (DMODEL / BK)        // 16
#define LDH 72                   // padded leading dim (halves)
#define STAGE_HALVES (2 * 128 * LDH)
#define GEMM_SMEM (STAGES * STAGE_HALVES * 2)   // 110592 bytes

// Flash-attention smem layout (bytes): all tiles [64][72] halves = 9216 B
#define FA_QS    0
#define FA_KS0   9216
#define FA_KS1   18432
#define FA_VS0   27648
#define FA_VS1   36864
#define FA_SMEM  46080

// Scratch (all fp16 activations)
__device__ __half g_xh [(size_t)M_ROWS * DMODEL];
__device__ __half g_wh [4 * (size_t)DMODEL * DMODEL];   // Wq,Wk,Wv,Wo
__device__ __half g_Qh [(size_t)BATCH_N * NH * T_SEQ * HD];
__device__ __half g_Kh [(size_t)BATCH_N * NH * T_SEQ * HD];
__device__ __half g_Vt [(size_t)BATCH_N * NH * HD * T_SEQ];  // [B,H,hd,T]
__device__ __half g_ctxh[(size_t)M_ROWS * DMODEL];

// ---------------------------------------------------------------------------
// Helpers
// ---------------------------------------------------------------------------
__device__ __forceinline__ uint32_t smem_u32(const void* p) {
    uint32_t a;
    asm("{ .reg .u64 t; cvta.to.shared.u64 t, %1; cvt.u32.u64 %0, t; }"
        : "=r"(a) : "l"(p));
    return a;
}
__device__ __forceinline__ float ex2(float x) {
    float y;
    asm("ex2.approx.f32 %0, %1;" : "=f"(y) : "f"(x));
    return y;
}
__device__ __forceinline__ void cpa16(uint32_t s, const void* g) {
    asm volatile("cp.async.cg.shared.global [%0], [%1], 16;" :: "r"(s), "l"(g));
}
__device__ __forceinline__ void cpa_commit() {
    asm volatile("cp.async.commit_group;");
}
__device__ __forceinline__ void mma_f16(float* d, const uint32_t* a,
                                        const uint32_t* b) {
    asm volatile(
        "mma.sync.aligned.m16n8k16.row.col.f32.f16.f16.f32 "
        "{%0,%1,%2,%3}, {%4,%5,%6,%7}, {%8,%9}, {%0,%1,%2,%3};"
        : "+f"(d[0]), "+f"(d[1]), "+f"(d[2]), "+f"(d[3])
        : "r"(a[0]), "r"(a[1]), "r"(a[2]), "r"(a[3]), "r"(b[0]), "r"(b[1]));
}
__device__ __forceinline__ void ldsm4(uint32_t& r0, uint32_t& r1,
                                      uint32_t& r2, uint32_t& r3, uint32_t a) {
    asm volatile("ldmatrix.sync.aligned.m8n8.x4.shared.b16 {%0,%1,%2,%3}, [%4];"
                 : "=r"(r0), "=r"(r1), "=r"(r2), "=r"(r3) : "r"(a));
}

// ---------------------------------------------------------------------------
// f32 -> fp16 RN conversion: x + all 4 weights in ONE launch
// ---------------------------------------------------------------------------
#define XN4 ((M_ROWS * DMODEL) / 4)     // 2097152
#define WN4 ((DMODEL * DMODEL) / 4)     // 262144

__global__ void __launch_bounds__(256)
cvt_all(const float4* __restrict__ x,
        const float4* __restrict__ w0, const float4* __restrict__ w1,
        const float4* __restrict__ w2, const float4* __restrict__ w3,
        uint2* __restrict__ xh, uint2* __restrict__ wh)
{
    int i = blockIdx.x * 256 + threadIdx.x;
    const float4* s;
    uint2* d;
    int o;
    if (i < XN4) { s = x; d = xh; o = i; }
    else {
        int j = i - XN4;
        int w = j / WN4;
        o = j - w * WN4;
        s = (w == 0) ? w0 : (w == 1) ? w1 : (w == 2) ? w2 : w3;
        d = wh + (size_t)w * WN4;
    }
    float4 v = s[o];
    __half2 h0 = __floats2half2_rn(v.x, v.y);
    __half2 h1 = __floats2half2_rn(v.z, v.w);
    d[o] = make_uint2(*(uint32_t*)&h0, *(uint32_t*)&h1);
}

// ---------------------------------------------------------------------------
// fp16 tensor-core GEMM (ldmatrix fragment loads)
// ---------------------------------------------------------------------------
__device__ __forceinline__ void load_stage(const __half* __restrict__ A,
                                           const __half* __restrict__ W,
                                           int m0, int n0, int kt,
                                           uint32_t sA, uint32_t sB, int tid)
{
#pragma unroll
    for (int p = 0; p < 4; p++) {
        int i = tid + p * 256;
        int r = i >> 3, c = i & 7;
        cpa16(sA + (uint32_t)(r * (LDH * 2) + c * 16),
              A + (size_t)(m0 + r) * DMODEL + kt * BK + c * 8);
    }
#pragma unroll
    for (int p = 0; p < 4; p++) {
        int i = tid + p * 256;
        int r = i >> 3, c = i & 7;
        cpa16(sB + (uint32_t)(r * (LDH * 2) + c * 16),
              W + (size_t)(n0 + r) * DMODEL + kt * BK + c * 8);
    }
}

template <bool SPLIT, bool BIAS>
__global__ void __launch_bounds__(256, 2)
gemm_fp16(const __half* __restrict__ A,
          const __half* __restrict__ W0, const __half* __restrict__ W1,
          const __half* __restrict__ W2,
          void* __restrict__ C0, void* __restrict__ C1, void* __restrict__ C2,
          const float* __restrict__ bias)
{
    extern __shared__ __align__(16) __half smem[];
    const uint32_t sbase = smem_u32(smem);

    const int tid  = threadIdx.x;
    const int wid  = tid >> 5;
    const int lane = tid & 31;
    const int warp_m = wid & 1;
    const int warp_n = wid >> 1;
    const int lr = lane >> 2;
    const int lc = lane & 3;

    const int m0 = blockIdx.y * BM;
    const int n0 = blockIdx.x * BN;
    const int z = blockIdx.z;
    const __half* W = (z == 0) ? W0 : (z == 1) ? W1 : W2;
    void* C = (z == 0) ? C0 : (z == 1) ? C1 : C2;

    // ldmatrix per-lane address offsets (bytes)
    const uint32_t a_off = (uint32_t)(((warp_m * 64 + (lane & 15)) * LDH
                                       + (lane >> 4) * 8) * 2);
    const uint32_t b_off = (uint32_t)(((warp_n * 32 + (lane & 7)
                                        + ((lane >> 4) & 1) * 8) * LDH
                                       + ((lane >> 3) & 1) * 8) * 2);

    float acc[4][4][4];
#pragma unroll
    for (int mi = 0; mi < 4; mi++)
#pragma unroll
        for (int ni = 0; ni < 4; ni++)
#pragma unroll
            for (int k = 0; k < 4; k++) acc[mi][ni][k] = 0.0f;

#pragma unroll
    for (int s = 0; s < STAGES; s++) {
        uint32_t sA = sbase + (uint32_t)(s * STAGE_HALVES) * 2;
        load_stage(A, W, m0, n0, s, sA, sA + 128 * LDH * 2, tid);
        cpa_commit();
    }

    for (int kt = 0; kt < NKT; kt++) {
        const int s = kt % STAGES;
        const uint32_t As_u = sbase + (uint32_t)(s * STAGE_HALVES) * 2;
        const uint32_t Bs_u = As_u + 128 * LDH * 2;

        asm volatile("cp.async.wait_group 2;");
        __syncthreads();

#pragma unroll
        for (int ks = 0; ks < 4; ks++) {       // 4 x k16
            uint32_t a[4][4], b[4][2];
#pragma unroll
            for (int mi = 0; mi < 4; mi++)
                ldsm4(a[mi][0], a[mi][1], a[mi][2], a[mi][3],
                      As_u + a_off + (uint32_t)((mi * 16 * LDH + ks * 16) * 2));
#pragma unroll
            for (int bp = 0; bp < 2; bp++)
                ldsm4(b[2 * bp][0], b[2 * bp][1], b[2 * bp + 1][0],
                      b[2 * bp + 1][1],
                      Bs_u + b_off + (uint32_t)((bp * 16 * LDH + ks * 16) * 2));
#pragma unroll
            for (int mi = 0; mi < 4; mi++)
#pragma unroll
                for (int ni = 0; ni < 4; ni++)
                    mma_f16(acc[mi][ni], a[mi], b[ni]);
        }

        __syncthreads();
        if (kt + STAGES < NKT) {
            uint32_t sA = sbase + (uint32_t)(s * STAGE_HALVES) * 2;
            load_stage(A, W, m0, n0, kt + STAGES, sA, sA + 128 * LDH * 2, tid);
        }
        cpa_commit();
    }

#pragma unroll
    for (int mi = 0; mi < 4; mi++) {
#pragma unroll
        for (int ni = 0; ni < 4; ni++) {
            const int n = n0 + warp_n * 32 + ni * 8 + lc * 2;
#pragma unroll
            for (int half_i = 0; half_i < 2; half_i++) {
                const int mg = m0 + warp_m * 64 + mi * 16 + lr + half_i * 8;
                float v0 = acc[mi][ni][half_i * 2 + 0];
                float v1 = acc[mi][ni][half_i * 2 + 1];
                if (SPLIT) {
                    const int bb = mg >> 11;
                    const int t  = mg & (T_SEQ - 1);
                    const int hh = n >> 6;
                    const int d0 = n & 63;
                    if (z == 2) {   // V: fp16, transposed [B,H,hd,T]
                        __half* Vt = (__half*)C;
                        size_t idx = (((size_t)(bb * NH + hh)) * HD + d0)
                                     * T_SEQ + t;
                        Vt[idx]         = __float2half_rn(v0);
                        Vt[idx + T_SEQ] = __float2half_rn(v1);
                    } else {        // Q/K: fp16 [B,H,T,hd]
                        __half* dst = (__half*)C
                            + (((size_t)(bb * NH + hh) * T_SEQ + t) * HD + d0);
                        *(__half2*)dst = __floats2half2_rn(v0, v1);
                    }
                } else {
                    if (BIAS) { v0 += bias[n]; v1 += bias[n + 1]; }
                    float* dst = (float*)C + (size_t)mg * DMODEL + n;
                    *(float2*)dst = make_float2(v0, v1);
                }
            }
        }
    }
}

// ---------------------------------------------------------------------------
// Tensor-core flash attention (causal), fp16, ldmatrix fragment loads
// ---------------------------------------------------------------------------
__device__ __forceinline__ void fa_load_kv(const __half* __restrict__ Kh,
                                           const __half* __restrict__ Vtg,
                                           uint32_t ks, uint32_t vs,
                                           size_t hb, size_t vb, int j0, int tid)
{
#pragma unroll
    for (int p = 0; p < 4; p++) {
        int i = p * 128 + tid;
        int r = i >> 3, c = i & 7;
        cpa16(ks + (uint32_t)(r * 144 + c * 16),
              Kh + hb + (size_t)(j0 + r) * HD + c * 8);
    }
#pragma unroll
    for (int p = 0; p < 4; p++) {
        int i = p * 128 + tid;
        int d = i >> 3, c = i & 7;
        cpa16(vs + (uint32_t)(d * 144 + c * 16),
              Vtg + vb + (size_t)d * T_SEQ + j0 + c * 8);
    }
}

__global__ void __launch_bounds__(128, 3)
flash_attn_tc(const __half* __restrict__ Qh, const __half* __restrict__ Kh,
              const __half* __restrict__ Vtg, __half* __restrict__ ctx)
{
    extern __shared__ __align__(16) char sm[];
    __half* Qs = (__half*)(sm + FA_QS);

    const int qt = (T_SEQ / 64 - 1) - blockIdx.x;   // heavy first
    const int h  = blockIdx.y;
    const int b  = blockIdx.z;
    const int i0 = qt * 64;
    const size_t hb = ((size_t)(b * NH + h)) * T_SEQ * HD;
    const size_t vb = ((size_t)(b * NH + h)) * HD * T_SEQ;

    const int tid  = threadIdx.x;
    const int wid  = tid >> 5;
    const int lane = tid & 31;
    const int lr = lane >> 2;
    const int lc = lane & 3;

    const uint32_t Qs_u  = smem_u32(sm) + FA_QS;
    const uint32_t Ks_u0 = smem_u32(sm) + FA_KS0;
    const uint32_t Vs_u0 = smem_u32(sm) + FA_VS0;

    // ldmatrix per-lane offsets (bytes); tile stride 72 halves = 144 B
    const uint32_t qa_off = (uint32_t)(((wid * 16 + (lane & 15)) * 72
                                        + (lane >> 4) * 8) * 2);
    const uint32_t kb_off = (uint32_t)((((lane & 7) + ((lane >> 4) & 1) * 8) * 72
                                        + ((lane >> 3) & 1) * 8) * 2);

    // Prologue: Q tile + KV tile 0
    {
#pragma unroll
        for (int p = 0; p < 4; p++) {
            int i = p * 128 + tid;
            int r = i >> 3, c = i & 7;
            cpa16(Qs_u + (uint32_t)(r * 144 + c * 16),
                  Qh + hb + (size_t)(i0 + r) * HD + c * 8);
        }
        fa_load_kv(Kh, Vtg, Ks_u0, Vs_u0, hb, vb, 0, tid);
        cpa_commit();
    }

    float m0 = -1e30f, m1 = -1e30f, l0 = 0.0f, l1 = 0.0f;
    float o[8][4];
#pragma unroll
    for (int nf = 0; nf < 8; nf++)
#pragma unroll
        for (int j = 0; j < 4; j++) o[nf][j] = 0.0f;

    const int qr = wid * 16 + lr;
    const float kk = 0.18033688011112042f;  // log2(e)/sqrt(64)

    for (int jt = 0; jt <= qt; jt++) {
        if (jt < qt) {
            const int nb = (jt + 1) & 1;
            fa_load_kv(Kh, Vtg, Ks_u0 + nb * 9216, Vs_u0 + nb * 9216,
                       hb, vb, (jt + 1) * 64, tid);
        }
        cpa_commit();
        asm volatile("cp.async.wait_group 1;");
        __syncthreads();

        const uint32_t Ks_u = Ks_u0 + (jt & 1) * 9216;
        const uint32_t Vs_u = Vs_u0 + (jt & 1) * 9216;

        // ---- S = Q @ K^T (fp16 mma, ldmatrix frags) ----
        float s[8][4];
#pragma unroll
        for (int nf = 0; nf < 8; nf++)
#pragma unroll
            for (int j = 0; j < 4; j++) s[nf][j] = 0.0f;

#pragma unroll
        for (int kc = 0; kc < 4; kc++) {
            uint32_t a[4];
            ldsm4(a[0], a[1], a[2], a[3], Qs_u + qa_off + kc * 32);
#pragma unroll
            for (int np = 0; np < 4; np++) {
                uint32_t b0, b1, b2, b3;
                ldsm4(b0, b1, b2, b3,
                      Ks_u + kb_off + (uint32_t)((np * 16 * 72 + kc * 16) * 2));
                uint32_t bl[2] = { b0, b1 };
                uint32_t bh[2] = { b2, b3 };
                mma_f16(s[2 * np],     a, bl);
                mma_f16(s[2 * np + 1], a, bh);
            }
        }

        // ---- online softmax (exp2 domain) ----
        const bool diag = (jt == qt);
        float mx0 = -1e30f, mx1 = -1e30f;
#pragma unroll
        for (int nf = 0; nf < 8; nf++) {
            float e0 = s[nf][0] * kk, e1 = s[nf][1] * kk;
            float e2 = s[nf][2] * kk, e3 = s[nf][3] * kk;
            if (diag) {
                const int c0 = nf * 8 + lc * 2, c1 = c0 + 1;
                if (c0 > qr)     e0 = -1e30f;
                if (c1 > qr)     e1 = -1e30f;
                if (c0 > qr + 8) e2 = -1e30f;
                if (c1 > qr + 8) e3 = -1e30f;
            }
            s[nf][0] = e0; s[nf][1] = e1; s[nf][2] = e2; s[nf][3] = e3;
            mx0 = fmaxf(mx0, fmaxf(e0, e1));
            mx1 = fmaxf(mx1, fmaxf(e2, e3));
        }
        mx0 = fmaxf(mx0, __shfl_xor_sync(0xffffffffu, mx0, 1));
        mx0 = fmaxf(mx0, __shfl_xor_sync(0xffffffffu, mx0, 2));
        mx1 = fmaxf(mx1, __shfl_xor_sync(0xffffffffu, mx1, 1));
        mx1 = fmaxf(mx1, __shfl_xor_sync(0xffffffffu, mx1, 2));

        const float mn0 = fmaxf(m0, mx0), mn1 = fmaxf(m1, mx1);
        const float al0 = ex2(m0 - mn0),  al1 = ex2(m1 - mn1);

        uint32_t ph[8][2];
        float sum0 = 0.0f, sum1 = 0.0f;
#pragma unroll
        for (int nf = 0; nf < 8; nf++) {
            float p0 = ex2(s[nf][0] - mn0), p1 = ex2(s[nf][1] - mn0);
            float p2 = ex2(s[nf][2] - mn1), p3 = ex2(s[nf][3] - mn1);
            sum0 += p0 + p1;
            sum1 += p2 + p3;
            __half2 hlo = __floats2half2_rn(p0, p1);
            __half2 hhi = __floats2half2_rn(p2, p3);
            ph[nf][0] = *(uint32_t*)&hlo;
            ph[nf][1] = *(uint32_t*)&hhi;
        }
        sum0 += __shfl_xor_sync(0xffffffffu, sum0, 1);
        sum0 += __shfl_xor_sync(0xffffffffu, sum0, 2);
        sum1 += __shfl_xor_sync(0xffffffffu, sum1, 1);
        sum1 += __shfl_xor_sync(0xffffffffu, sum1, 2);
        l0 = l0 * al0 + sum0;
        l1 = l1 * al1 + sum1;
        m0 = mn0; m1 = mn1;
#pragma unroll
        for (int nf = 0; nf < 8; nf++) {
            o[nf][0] *= al0; o[nf][1] *= al0;
            o[nf][2] *= al1; o[nf][3] *= al1;
        }

        // ---- O += P @ V (fp16 mma, ldmatrix V frags) ----
#pragma unroll
        for (int kc = 0; kc < 4; kc++) {
            uint32_t a[4] = { ph[2 * kc][0], ph[2 * kc][1],
                              ph[2 * kc + 1][0], ph[2 * kc + 1][1] };
#pragma unroll
            for (int np = 0; np < 4; np++) {
                uint32_t b0, b1, b2, b3;
                ldsm4(b0, b1, b2, b3,
                      Vs_u + kb_off + (uint32_t)((np * 16 * 72 + kc * 16) * 2));
                uint32_t bl[2] = { b0, b1 };
                uint32_t bh[2] = { b2, b3 };
                mma_f16(o[2 * np],     a, bl);
                mma_f16(o[2 * np + 1], a, bh);
            }
        }
        __syncthreads();
    }

    // ---- epilogue: normalize, fp16 ctx [B*T, DMODEL] ----
    const float inv0 = 1.0f / l0, inv1 = 1.0f / l1;
    const int t_lo = i0 + qr;
#pragma unroll
    for (int nf = 0; nf < 8; nf++) {
        const int d = nf * 8 + lc * 2;
        __half* p0 = ctx + ((size_t)(b * T_SEQ + t_lo)) * DMODEL + h * HD + d;
        *(__half2*)p0 = __floats2half2_rn(o[nf][0] * inv0, o[nf][1] * inv0);
        __half* p1 = p0 + (size_t)8 * DMODEL;
        *(__half2*)p1 = __floats2half2_rn(o[nf][2] * inv1, o[nf][3] * inv1);
    }
}

// ---------------------------------------------------------------------------

extern "C" void kernel_launch(void* const* d_in, const int* in_sizes, int n_in,
                              void* d_out, int out_size)
{
    const float* x  = (const float*)d_in[0];
    const float* wq = (const float*)d_in[1];
    const float* wk = (const float*)d_in[2];
    const float* wv = (const float*)d_in[3];
    const float* wo = (const float*)d_in[4];
    const float* bo = (const float*)d_in[5];
    float* out = (float*)d_out;

    __half *pXh, *pWh, *pQh, *pKh, *pVt, *pCtx;
    cudaGetSymbolAddress((void**)&pXh, g_xh);
    cudaGetSymbolAddress((void**)&pWh, g_wh);
    cudaGetSymbolAddress((void**)&pQh, g_Qh);
    cudaGetSymbolAddress((void**)&pKh, g_Kh);
    cudaGetSymbolAddress((void**)&pVt, g_Vt);
    cudaGetSymbolAddress((void**)&pCtx, g_ctxh);

    __half* pWq = pWh;
    __half* pWk = pWh + (size_t)DMODEL * DMODEL;
    __half* pWv = pWh + 2 * (size_t)DMODEL * DMODEL;
    __half* pWo = pWh + 3 * (size_t)DMODEL * DMODEL;

    cudaFuncSetAttribute(gemm_fp16<true, false>,
                         cudaFuncAttributeMaxDynamicSharedMemorySize, GEMM_SMEM);
    cudaFuncSetAttribute(gemm_fp16<false, true>,
                         cudaFuncAttributeMaxDynamicSharedMemorySize, GEMM_SMEM);
    cudaFuncSetAttribute(flash_attn_tc,
                         cudaFuncAttributeMaxDynamicSharedMemorySize, FA_SMEM);

    // 1) single-launch f32->fp16 conversion (x + 4 weights)
    {
        int total = XN4 + 4 * WN4;
        cvt_all<<<total / 256, 256>>>(
            (const float4*)x, (const float4*)wq, (const float4*)wk,
            (const float4*)wv, (const float4*)wo, (uint2*)pXh, (uint2*)pWh);
    }

    // 2) fused QKV projections (fp16 MMA); Q/K split-head, V transposed
    {
        dim3 grid(DMODEL / BN, M_ROWS / BM, 3);
        gemm_fp16<true, false><<<grid, 256, GEMM_SMEM>>>(
            pXh, pWq, pWk, pWv, pQh, pKh, pVt, nullptr);
    }

    // 3) tensor-core flash attention (fp16)
    {
        dim3 fgrid(T_SEQ / 64, NH, BATCH_N);
        flash_attn_tc<<<fgrid, 128, FA_SMEM>>>(pQh, pKh, pVt, pCtx);
    }

    // 4) output projection + bias (fp32 out)
    {
        dim3 grid(DMODEL / BN, M_ROWS / BM, 1);
        gemm_fp16<false, true><<<grid, 256, GEMM_SMEM>>>(
            pCtx, pWo, pWo, pWo, out, out, out, bo);
    }
}

// round 7
// speedup vs baseline: 8.0826x; 1.0196x over previous
#include <cuda_runtime.h>
#include <cuda_fp16.h>
#include <cstdint>
#include <cstddef>

// Problem constants
#define BATCH_N 4
#define T_SEQ   2048
#define NH      16
#define HD      64
#define DMODEL  1024
#define M_ROWS  (BATCH_N * T_SEQ)   // 8192

// GEMM tiling (mma.sync m16n8k16 fp16)
#define BM 128
#define BN 128
#define BK 64
#define STAGES 3
#define NKT (DMODEL / BK)        // 16
#define LDH 72                   // padded leading dim (halves)
#define STAGE_HALVES (2 * 128 * LDH)
#define GEMM_SMEM (STAGES * STAGE_HALVES * 2)   // 110592 bytes

// Flash-attention smem layout (bytes): all tiles [64][72] halves = 9216 B
#define FA_QS    0
#define FA_KS0   9216
#define FA_KS1   18432
#define FA_VS0   27648
#define FA_VS1   36864
#define FA_SMEM  46080

// Scratch (all fp16 activations)
__device__ __half g_xh [(size_t)M_ROWS * DMODEL];
__device__ __half g_wh [4 * (size_t)DMODEL * DMODEL];   // Wq,Wk,Wv,Wo
__device__ __half g_Qh [(size_t)BATCH_N * NH * T_SEQ * HD];
__device__ __half g_Kh [(size_t)BATCH_N * NH * T_SEQ * HD];
__device__ __half g_Vt [(size_t)BATCH_N * NH * HD * T_SEQ];  // [B,H,hd,T]
__device__ __half g_ctxh[(size_t)M_ROWS * DMODEL];

// ---------------------------------------------------------------------------
// Helpers
// ---------------------------------------------------------------------------
__device__ __forceinline__ uint32_t smem_u32(const void* p) {
    uint32_t a;
    asm("{ .reg .u64 t; cvta.to.shared.u64 t, %1; cvt.u32.u64 %0, t; }"
        : "=r"(a) : "l"(p));
    return a;
}
__device__ __forceinline__ float ex2(float x) {
    float y;
    asm("ex2.approx.f32 %0, %1;" : "=f"(y) : "f"(x));
    return y;
}
__device__ __forceinline__ void cpa16(uint32_t s, const void* g) {
    asm volatile("cp.async.cg.shared.global [%0], [%1], 16;" :: "r"(s), "l"(g));
}
__device__ __forceinline__ void cpa_commit() {
    asm volatile("cp.async.commit_group;");
}
__device__ __forceinline__ void mma_f16(float* d, const uint32_t* a,
                                        const uint32_t* b) {
    asm volatile(
        "mma.sync.aligned.m16n8k16.row.col.f32.f16.f16.f32 "
        "{%0,%1,%2,%3}, {%4,%5,%6,%7}, {%8,%9}, {%0,%1,%2,%3};"
        : "+f"(d[0]), "+f"(d[1]), "+f"(d[2]), "+f"(d[3])
        : "r"(a[0]), "r"(a[1]), "r"(a[2]), "r"(a[3]), "r"(b[0]), "r"(b[1]));
}
__device__ __forceinline__ void ldsm4(uint32_t& r0, uint32_t& r1,
                                      uint32_t& r2, uint32_t& r3, uint32_t a) {
    asm volatile("ldmatrix.sync.aligned.m8n8.x4.shared.b16 {%0,%1,%2,%3}, [%4];"
                 : "=r"(r0), "=r"(r1), "=r"(r2), "=r"(r3) : "r"(a));
}

// ---------------------------------------------------------------------------
// f32 -> fp16 RN conversion: x + all 4 weights in ONE launch
// ---------------------------------------------------------------------------
#define XN4 ((M_ROWS * DMODEL) / 4)     // 2097152
#define WN4 ((DMODEL * DMODEL) / 4)     // 262144

__global__ void __launch_bounds__(256)
cvt_all(const float4* __restrict__ x,
        const float4* __restrict__ w0, const float4* __restrict__ w1,
        const float4* __restrict__ w2, const float4* __restrict__ w3,
        uint2* __restrict__ xh, uint2* __restrict__ wh)
{
    int i = blockIdx.x * 256 + threadIdx.x;
    const float4* s;
    uint2* d;
    int o;
    if (i < XN4) { s = x; d = xh; o = i; }
    else {
        int j = i - XN4;
        int w = j / WN4;
        o = j - w * WN4;
        s = (w == 0) ? w0 : (w == 1) ? w1 : (w == 2) ? w2 : w3;
        d = wh + (size_t)w * WN4;
    }
    float4 v = s[o];
    __half2 h0 = __floats2half2_rn(v.x, v.y);
    __half2 h1 = __floats2half2_rn(v.z, v.w);
    d[o] = make_uint2(*(uint32_t*)&h0, *(uint32_t*)&h1);
}

// ---------------------------------------------------------------------------
// fp16 tensor-core GEMM, single-barrier multistage pipeline
// ---------------------------------------------------------------------------
__device__ __forceinline__ void load_stage(const __half* __restrict__ A,
                                           const __half* __restrict__ W,
                                           int m0, int n0, int kt,
                                           uint32_t sA, uint32_t sB, int tid)
{
#pragma unroll
    for (int p = 0; p < 4; p++) {
        int i = tid + p * 256;
        int r = i >> 3, c = i & 7;
        cpa16(sA + (uint32_t)(r * (LDH * 2) + c * 16),
              A + (size_t)(m0 + r) * DMODEL + kt * BK + c * 8);
    }
#pragma unroll
    for (int p = 0; p < 4; p++) {
        int i = tid + p * 256;
        int r = i >> 3, c = i & 7;
        cpa16(sB + (uint32_t)(r * (LDH * 2) + c * 16),
              W + (size_t)(n0 + r) * DMODEL + kt * BK + c * 8);
    }
}

template <bool SPLIT, bool BIAS>
__global__ void __launch_bounds__(256, 2)
gemm_fp16(const __half* __restrict__ A,
          const __half* __restrict__ W0, const __half* __restrict__ W1,
          const __half* __restrict__ W2,
          void* __restrict__ C0, void* __restrict__ C1, void* __restrict__ C2,
          const float* __restrict__ bias)
{
    extern __shared__ __align__(16) __half smem[];
    const uint32_t sbase = smem_u32(smem);

    const int tid  = threadIdx.x;
    const int wid  = tid >> 5;
    const int lane = tid & 31;
    const int warp_m = wid & 1;
    const int warp_n = wid >> 1;
    const int lr = lane >> 2;
    const int lc = lane & 3;

    const int m0 = blockIdx.y * BM;
    const int n0 = blockIdx.x * BN;
    const int z = blockIdx.z;
    const __half* W = (z == 0) ? W0 : (z == 1) ? W1 : W2;
    void* C = (z == 0) ? C0 : (z == 1) ? C1 : C2;

    // ldmatrix per-lane address offsets (bytes)
    const uint32_t a_off = (uint32_t)(((warp_m * 64 + (lane & 15)) * LDH
                                       + (lane >> 4) * 8) * 2);
    const uint32_t b_off = (uint32_t)(((warp_n * 32 + (lane & 7)
                                        + ((lane >> 4) & 1) * 8) * LDH
                                       + ((lane >> 3) & 1) * 8) * 2);

    float acc[4][4][4];
#pragma unroll
    for (int mi = 0; mi < 4; mi++)
#pragma unroll
        for (int ni = 0; ni < 4; ni++)
#pragma unroll
            for (int k = 0; k < 4; k++) acc[mi][ni][k] = 0.0f;

    // Prefill STAGES-1 tiles (one free slot for single-barrier rotation)
#pragma unroll
    for (int s = 0; s < STAGES - 1; s++) {
        uint32_t sA = sbase + (uint32_t)(s * STAGE_HALVES) * 2;
        load_stage(A, W, m0, n0, s, sA, sA + 128 * LDH * 2, tid);
        cpa_commit();
    }

    for (int kt = 0; kt < NKT; kt++) {
        // stage kt%STAGES ready after this wait; ONE barrier per iteration
        asm volatile("cp.async.wait_group %0;" :: "n"(STAGES - 2));
        __syncthreads();

        // Issue loads for tile kt+STAGES-1 into the free slot: its previous
        // reads (tile kt-1) finished before the barrier above.
        const int wt = kt + STAGES - 1;
        if (wt < NKT) {
            const int ws = wt % STAGES;
            uint32_t sA = sbase + (uint32_t)(ws * STAGE_HALVES) * 2;
            load_stage(A, W, m0, n0, wt, sA, sA + 128 * LDH * 2, tid);
        }
        cpa_commit();

        // Compute on stage kt%STAGES (overlaps the cp.async just issued)
        const int s = kt % STAGES;
        const uint32_t As_u = sbase + (uint32_t)(s * STAGE_HALVES) * 2;
        const uint32_t Bs_u = As_u + 128 * LDH * 2;

#pragma unroll
        for (int ks = 0; ks < 4; ks++) {       // 4 x k16
            uint32_t a[4][4], b[4][2];
#pragma unroll
            for (int mi = 0; mi < 4; mi++)
                ldsm4(a[mi][0], a[mi][1], a[mi][2], a[mi][3],
                      As_u + a_off + (uint32_t)((mi * 16 * LDH + ks * 16) * 2));
#pragma unroll
            for (int bp = 0; bp < 2; bp++)
                ldsm4(b[2 * bp][0], b[2 * bp][1], b[2 * bp + 1][0],
                      b[2 * bp + 1][1],
                      Bs_u + b_off + (uint32_t)((bp * 16 * LDH + ks * 16) * 2));
#pragma unroll
            for (int mi = 0; mi < 4; mi++)
#pragma unroll
                for (int ni = 0; ni < 4; ni++)
                    mma_f16(acc[mi][ni], a[mi], b[ni]);
        }
    }

#pragma unroll
    for (int mi = 0; mi < 4; mi++) {
#pragma unroll
        for (int ni = 0; ni < 4; ni++) {
            const int n = n0 + warp_n * 32 + ni * 8 + lc * 2;
#pragma unroll
            for (int half_i = 0; half_i < 2; half_i++) {
                const int mg = m0 + warp_m * 64 + mi * 16 + lr + half_i * 8;
                float v0 = acc[mi][ni][half_i * 2 + 0];
                float v1 = acc[mi][ni][half_i * 2 + 1];
                if (SPLIT) {
                    const int bb = mg >> 11;
                    const int t  = mg & (T_SEQ - 1);
                    const int hh = n >> 6;
                    const int d0 = n & 63;
                    if (z == 2) {   // V: fp16, transposed [B,H,hd,T]
                        __half* Vt = (__half*)C;
                        size_t idx = (((size_t)(bb * NH + hh)) * HD + d0)
                                     * T_SEQ + t;
                        Vt[idx]         = __float2half_rn(v0);
                        Vt[idx + T_SEQ] = __float2half_rn(v1);
                    } else {        // Q/K: fp16 [B,H,T,hd]
                        __half* dst = (__half*)C
                            + (((size_t)(bb * NH + hh) * T_SEQ + t) * HD + d0);
                        *(__half2*)dst = __floats2half2_rn(v0, v1);
                    }
                } else {
                    if (BIAS) { v0 += bias[n]; v1 += bias[n + 1]; }
                    float* dst = (float*)C + (size_t)mg * DMODEL + n;
                    *(float2*)dst = make_float2(v0, v1);
                }
            }
        }
    }
}

// ---------------------------------------------------------------------------
// Tensor-core flash attention (causal), fp16, ldmatrix fragment loads
// ---------------------------------------------------------------------------
__device__ __forceinline__ void fa_load_kv(const __half* __restrict__ Kh,
                                           const __half* __restrict__ Vtg,
                                           uint32_t ks, uint32_t vs,
                                           size_t hb, size_t vb, int j0, int tid)
{
#pragma unroll
    for (int p = 0; p < 4; p++) {
        int i = p * 128 + tid;
        int r = i >> 3, c = i & 7;
        cpa16(ks + (uint32_t)(r * 144 + c * 16),
              Kh + hb + (size_t)(j0 + r) * HD + c * 8);
    }
#pragma unroll
    for (int p = 0; p < 4; p++) {
        int i = p * 128 + tid;
        int d = i >> 3, c = i & 7;
        cpa16(vs + (uint32_t)(d * 144 + c * 16),
              Vtg + vb + (size_t)d * T_SEQ + j0 + c * 8);
    }
}

__global__ void __launch_bounds__(128, 4)
flash_attn_tc(const __half* __restrict__ Qh, const __half* __restrict__ Kh,
              const __half* __restrict__ Vtg, __half* __restrict__ ctx)
{
    extern __shared__ __align__(16) char sm[];

    const int qt = (T_SEQ / 64 - 1) - blockIdx.x;   // heavy first
    const int h  = blockIdx.y;
    const int b  = blockIdx.z;
    const int i0 = qt * 64;
    const size_t hb = ((size_t)(b * NH + h)) * T_SEQ * HD;
    const size_t vb = ((size_t)(b * NH + h)) * HD * T_SEQ;

    const int tid  = threadIdx.x;
    const int wid  = tid >> 5;
    const int lane = tid & 31;
    const int lr = lane >> 2;
    const int lc = lane & 3;

    const uint32_t Qs_u  = smem_u32(sm) + FA_QS;
    const uint32_t Ks_u0 = smem_u32(sm) + FA_KS0;
    const uint32_t Vs_u0 = smem_u32(sm) + FA_VS0;

    const uint32_t qa_off = (uint32_t)(((wid * 16 + (lane & 15)) * 72
                                        + (lane >> 4) * 8) * 2);
    const uint32_t kb_off = (uint32_t)((((lane & 7) + ((lane >> 4) & 1) * 8) * 72
                                        + ((lane >> 3) & 1) * 8) * 2);

    // Prologue: Q tile + KV tile 0
    {
#pragma unroll
        for (int p = 0; p < 4; p++) {
            int i = p * 128 + tid;
            int r = i >> 3, c = i & 7;
            cpa16(Qs_u + (uint32_t)(r * 144 + c * 16),
                  Qh + hb + (size_t)(i0 + r) * HD + c * 8);
        }
        fa_load_kv(Kh, Vtg, Ks_u0, Vs_u0, hb, vb, 0, tid);
        cpa_commit();
    }

    float m0 = -1e30f, m1 = -1e30f, l0 = 0.0f, l1 = 0.0f;
    float o[8][4];
#pragma unroll
    for (int nf = 0; nf < 8; nf++)
#pragma unroll
        for (int j = 0; j < 4; j++) o[nf][j] = 0.0f;

    const int qr = wid * 16 + lr;
    const float kk = 0.18033688011112042f;  // log2(e)/sqrt(64)

    for (int jt = 0; jt <= qt; jt++) {
        if (jt < qt) {
            const int nb = (jt + 1) & 1;
            fa_load_kv(Kh, Vtg, Ks_u0 + nb * 9216, Vs_u0 + nb * 9216,
                       hb, vb, (jt + 1) * 64, tid);
        }
        cpa_commit();
        asm volatile("cp.async.wait_group 1;");
        __syncthreads();

        const uint32_t Ks_u = Ks_u0 + (jt & 1) * 9216;
        const uint32_t Vs_u = Vs_u0 + (jt & 1) * 9216;

        // ---- S = Q @ K^T ----
        float s[8][4];
#pragma unroll
        for (int nf = 0; nf < 8; nf++)
#pragma unroll
            for (int j = 0; j < 4; j++) s[nf][j] = 0.0f;

#pragma unroll
        for (int kc = 0; kc < 4; kc++) {
            uint32_t a[4];
            ldsm4(a[0], a[1], a[2], a[3], Qs_u + qa_off + kc * 32);
#pragma unroll
            for (int np = 0; np < 4; np++) {
                uint32_t b0, b1, b2, b3;
                ldsm4(b0, b1, b2, b3,
                      Ks_u + kb_off + (uint32_t)((np * 16 * 72 + kc * 16) * 2));
                uint32_t bl[2] = { b0, b1 };
                uint32_t bh[2] = { b2, b3 };
                mma_f16(s[2 * np],     a, bl);
                mma_f16(s[2 * np + 1], a, bh);
            }
        }

        // ---- online softmax (exp2 domain) ----
        const bool diag = (jt == qt);
        float mx0 = -1e30f, mx1 = -1e30f;
#pragma unroll
        for (int nf = 0; nf < 8; nf++) {
            float e0 = s[nf][0] * kk, e1 = s[nf][1] * kk;
            float e2 = s[nf][2] * kk, e3 = s[nf][3] * kk;
            if (diag) {
                const int c0 = nf * 8 + lc * 2, c1 = c0 + 1;
                if (c0 > qr)     e0 = -1e30f;
                if (c1 > qr)     e1 = -1e30f;
                if (c0 > qr + 8) e2 = -1e30f;
                if (c1 > qr + 8) e3 = -1e30f;
            }
            s[nf][0] = e0; s[nf][1] = e1; s[nf][2] = e2; s[nf][3] = e3;
            mx0 = fmaxf(mx0, fmaxf(e0, e1));
            mx1 = fmaxf(mx1, fmaxf(e2, e3));
        }
        mx0 = fmaxf(mx0, __shfl_xor_sync(0xffffffffu, mx0, 1));
        mx0 = fmaxf(mx0, __shfl_xor_sync(0xffffffffu, mx0, 2));
        mx1 = fmaxf(mx1, __shfl_xor_sync(0xffffffffu, mx1, 1));
        mx1 = fmaxf(mx1, __shfl_xor_sync(0xffffffffu, mx1, 2));

        const float mn0 = fmaxf(m0, mx0), mn1 = fmaxf(m1, mx1);
        const float al0 = ex2(m0 - mn0),  al1 = ex2(m1 - mn1);

        uint32_t ph[8][2];
        float sum0 = 0.0f, sum1 = 0.0f;
#pragma unroll
        for (int nf = 0; nf < 8; nf++) {
            float p0 = ex2(s[nf][0] - mn0), p1 = ex2(s[nf][1] - mn0);
            float p2 = ex2(s[nf][2] - mn1), p3 = ex2(s[nf][3] - mn1);
            sum0 += p0 + p1;
            sum1 += p2 + p3;
            __half2 hlo = __floats2half2_rn(p0, p1);
            __half2 hhi = __floats2half2_rn(p2, p3);
            ph[nf][0] = *(uint32_t*)&hlo;
            ph[nf][1] = *(uint32_t*)&hhi;
        }
        sum0 += __shfl_xor_sync(0xffffffffu, sum0, 1);
        sum0 += __shfl_xor_sync(0xffffffffu, sum0, 2);
        sum1 += __shfl_xor_sync(0xffffffffu, sum1, 1);
        sum1 += __shfl_xor_sync(0xffffffffu, sum1, 2);
        l0 = l0 * al0 + sum0;
        l1 = l1 * al1 + sum1;
        m0 = mn0; m1 = mn1;
#pragma unroll
        for (int nf = 0; nf < 8; nf++) {
            o[nf][0] *= al0; o[nf][1] *= al0;
            o[nf][2] *= al1; o[nf][3] *= al1;
        }

        // ---- O += P @ V ----
#pragma unroll
        for (int kc = 0; kc < 4; kc++) {
            uint32_t a[4] = { ph[2 * kc][0], ph[2 * kc][1],
                              ph[2 * kc + 1][0], ph[2 * kc + 1][1] };
#pragma unroll
            for (int np = 0; np < 4; np++) {
                uint32_t b0, b1, b2, b3;
                ldsm4(b0, b1, b2, b3,
                      Vs_u + kb_off + (uint32_t)((np * 16 * 72 + kc * 16) * 2));
                uint32_t bl[2] = { b0, b1 };
                uint32_t bh[2] = { b2, b3 };
                mma_f16(o[2 * np],     a, bl);
                mma_f16(o[2 * np + 1], a, bh);
            }
        }
        __syncthreads();
    }

    // ---- epilogue ----
    const float inv0 = 1.0f / l0, inv1 = 1.0f / l1;
    const int t_lo = i0 + qr;
#pragma unroll
    for (int nf = 0; nf < 8; nf++) {
        const int d = nf * 8 + lc * 2;
        __half* p0 = ctx + ((size_t)(b * T_SEQ + t_lo)) * DMODEL + h * HD + d;
        *(__half2*)p0 = __floats2half2_rn(o[nf][0] * inv0, o[nf][1] * inv0);
        __half* p1 = p0 + (size_t)8 * DMODEL;
        *(__half2*)p1 = __floats2half2_rn(o[nf][2] * inv1, o[nf][3] * inv1);
    }
}

// ---------------------------------------------------------------------------

extern "C" void kernel_launch(void* const* d_in, const int* in_sizes, int n_in,
                              void* d_out, int out_size)
{
    const float* x  = (const float*)d_in[0];
    const float* wq = (const float*)d_in[1];
    const float* wk = (const float*)d_in[2];
    const float* wv = (const float*)d_in[3];
    const float* wo = (const float*)d_in[4];
    const float* bo = (const float*)d_in[5];
    float* out = (float*)d_out;

    __half *pXh, *pWh, *pQh, *pKh, *pVt, *pCtx;
    cudaGetSymbolAddress((void**)&pXh, g_xh);
    cudaGetSymbolAddress((void**)&pWh, g_wh);
    cudaGetSymbolAddress((void**)&pQh, g_Qh);
    cudaGetSymbolAddress((void**)&pKh, g_Kh);
    cudaGetSymbolAddress((void**)&pVt, g_Vt);
    cudaGetSymbolAddress((void**)&pCtx, g_ctxh);

    __half* pWq = pWh;
    __half* pWk = pWh + (size_t)DMODEL * DMODEL;
    __half* pWv = pWh + 2 * (size_t)DMODEL * DMODEL;
    __half* pWo = pWh + 3 * (size_t)DMODEL * DMODEL;

    cudaFuncSetAttribute(gemm_fp16<true, false>,
                         cudaFuncAttributeMaxDynamicSharedMemorySize, GEMM_SMEM);
    cudaFuncSetAttribute(gemm_fp16<false, true>,
                         cudaFuncAttributeMaxDynamicSharedMemorySize, GEMM_SMEM);
    cudaFuncSetAttribute(flash_attn_tc,
                         cudaFuncAttributeMaxDynamicSharedMemorySize, FA_SMEM);

    // 1) single-launch f32->fp16 conversion (x + 4 weights)
    {
        int total = XN4 + 4 * WN4;
        cvt_all<<<total / 256, 256>>>(
            (const float4*)x, (const float4*)wq, (const float4*)wk,
            (const float4*)wv, (const float4*)wo, (uint2*)pXh, (uint2*)pWh);
    }

    // 2) fused QKV projections (fp16 MMA); Q/K split-head, V transposed
    {
        dim3 grid(DMODEL / BN, M_ROWS / BM, 3);
        gemm_fp16<true, false><<<grid, 256, GEMM_SMEM>>>(
            pXh, pWq, pWk, pWv, pQh, pKh, pVt, nullptr);
    }

    // 3) tensor-core flash attention (fp16)
    {
        dim3 fgrid(T_SEQ / 64, NH, BATCH_N);
        flash_attn_tc<<<fgrid, 128, FA_SMEM>>>(pQh, pKh, pVt, pCtx);
    }

    // 4) output projection + bias (fp32 out)
    {
        dim3 grid(DMODEL / BN, M_ROWS / BM, 1);
        gemm_fp16<false, true><<<grid, 256, GEMM_SMEM>>>(
            pCtx, pWo, pWo, pWo, out, out, out, bo);
    }
}

// round 8
// speedup vs baseline: 8.1335x; 1.0063x over previous
#include <cuda_runtime.h>
#include <cuda_fp16.h>
#include <cstdint>
#include <cstddef>

// Problem constants
#define BATCH_N 4
#define T_SEQ   2048
#define NH      16
#define HD      64
#define DMODEL  1024
#define M_ROWS  (BATCH_N * T_SEQ)   // 8192

// GEMM tiling (mma.sync m16n8k16 fp16)
#define BM 128
#define BN 128
#define BK 64
#define STAGES 3
#define NKT (DMODEL / BK)        // 16
#define LDH 72                   // padded leading dim (halves)
#define STAGE_HALVES (2 * 128 * LDH)
#define GEMM_SMEM (STAGES * STAGE_HALVES * 2)   // 110592 bytes
#define LDO 136                  // output staging pad (halves)

// Flash-attention smem layout (bytes): all tiles [64][72] halves = 9216 B
#define FA_QS    0
#define FA_KS0   9216
#define FA_KS1   18432
#define FA_VS0   27648
#define FA_VS1   36864
#define FA_SMEM  46080

// Scratch (all fp16 activations)
__device__ __half g_xh [(size_t)M_ROWS * DMODEL];
__device__ __half g_wh [4 * (size_t)DMODEL * DMODEL];   // Wq,Wk,Wv,Wo
__device__ __half g_Qh [(size_t)BATCH_N * NH * T_SEQ * HD];
__device__ __half g_Kh [(size_t)BATCH_N * NH * T_SEQ * HD];
__device__ __half g_Vt [(size_t)BATCH_N * NH * HD * T_SEQ];  // [B,H,hd,T]
__device__ __half g_ctxh[(size_t)M_ROWS * DMODEL];

// ---------------------------------------------------------------------------
// Helpers
// ---------------------------------------------------------------------------
__device__ __forceinline__ uint32_t smem_u32(const void* p) {
    uint32_t a;
    asm("{ .reg .u64 t; cvta.to.shared.u64 t, %1; cvt.u32.u64 %0, t; }"
        : "=r"(a) : "l"(p));
    return a;
}
__device__ __forceinline__ float ex2(float x) {
    float y;
    asm("ex2.approx.f32 %0, %1;" : "=f"(y) : "f"(x));
    return y;
}
__device__ __forceinline__ void cpa16(uint32_t s, const void* g) {
    asm volatile("cp.async.cg.shared.global [%0], [%1], 16;" :: "r"(s), "l"(g));
}
__device__ __forceinline__ void cpa_commit() {
    asm volatile("cp.async.commit_group;");
}
__device__ __forceinline__ void mma_f16(float* d, const uint32_t* a,
                                        const uint32_t* b) {
    asm volatile(
        "mma.sync.aligned.m16n8k16.row.col.f32.f16.f16.f32 "
        "{%0,%1,%2,%3}, {%4,%5,%6,%7}, {%8,%9}, {%0,%1,%2,%3};"
        : "+f"(d[0]), "+f"(d[1]), "+f"(d[2]), "+f"(d[3])
        : "r"(a[0]), "r"(a[1]), "r"(a[2]), "r"(a[3]), "r"(b[0]), "r"(b[1]));
}
__device__ __forceinline__ void ldsm4(uint32_t& r0, uint32_t& r1,
                                      uint32_t& r2, uint32_t& r3, uint32_t a) {
    asm volatile("ldmatrix.sync.aligned.m8n8.x4.shared.b16 {%0,%1,%2,%3}, [%4];"
                 : "=r"(r0), "=r"(r1), "=r"(r2), "=r"(r3) : "r"(a));
}

// ---------------------------------------------------------------------------
// f32 -> fp16 RN conversion: x + all 4 weights in ONE launch
// ---------------------------------------------------------------------------
#define XN4 ((M_ROWS * DMODEL) / 4)     // 2097152
#define WN4 ((DMODEL * DMODEL) / 4)     // 262144

__global__ void __launch_bounds__(256)
cvt_all(const float4* __restrict__ x,
        const float4* __restrict__ w0, const float4* __restrict__ w1,
        const float4* __restrict__ w2, const float4* __restrict__ w3,
        uint2* __restrict__ xh, uint2* __restrict__ wh)
{
    int i = blockIdx.x * 256 + threadIdx.x;
    const float4* s;
    uint2* d;
    int o;
    if (i < XN4) { s = x; d = xh; o = i; }
    else {
        int j = i - XN4;
        int w = j / WN4;
        o = j - w * WN4;
        s = (w == 0) ? w0 : (w == 1) ? w1 : (w == 2) ? w2 : w3;
        d = wh + (size_t)w * WN4;
    }
    float4 v = s[o];
    __half2 h0 = __floats2half2_rn(v.x, v.y);
    __half2 h1 = __floats2half2_rn(v.z, v.w);
    d[o] = make_uint2(*(uint32_t*)&h0, *(uint32_t*)&h1);
}

// ---------------------------------------------------------------------------
// fp16 tensor-core GEMM, single-barrier multistage pipeline.
// SPLIT epilogue stages the tile through smem for coalesced STG.128.
// ---------------------------------------------------------------------------
__device__ __forceinline__ void load_stage(const __half* __restrict__ A,
                                           const __half* __restrict__ W,
                                           int m0, int n0, int kt,
                                           uint32_t sA, uint32_t sB, int tid)
{
#pragma unroll
    for (int p = 0; p < 4; p++) {
        int i = tid + p * 256;
        int r = i >> 3, c = i & 7;
        cpa16(sA + (uint32_t)(r * (LDH * 2) + c * 16),
              A + (size_t)(m0 + r) * DMODEL + kt * BK + c * 8);
    }
#pragma unroll
    for (int p = 0; p < 4; p++) {
        int i = tid + p * 256;
        int r = i >> 3, c = i & 7;
        cpa16(sB + (uint32_t)(r * (LDH * 2) + c * 16),
              W + (size_t)(n0 + r) * DMODEL + kt * BK + c * 8);
    }
}

template <bool SPLIT, bool BIAS>
__global__ void __launch_bounds__(256, 2)
gemm_fp16(const __half* __restrict__ A,
          const __half* __restrict__ W0, const __half* __restrict__ W1,
          const __half* __restrict__ W2,
          void* __restrict__ C0, void* __restrict__ C1, void* __restrict__ C2,
          const float* __restrict__ bias)
{
    extern __shared__ __align__(16) __half smem[];
    const uint32_t sbase = smem_u32(smem);

    const int tid  = threadIdx.x;
    const int wid  = tid >> 5;
    const int lane = tid & 31;
    const int warp_m = wid & 1;
    const int warp_n = wid >> 1;
    const int lr = lane >> 2;
    const int lc = lane & 3;

    const int m0 = blockIdx.y * BM;
    const int n0 = blockIdx.x * BN;
    const int z = blockIdx.z;
    const __half* W = (z == 0) ? W0 : (z == 1) ? W1 : W2;
    void* C = (z == 0) ? C0 : (z == 1) ? C1 : C2;

    // ldmatrix per-lane address offsets (bytes)
    const uint32_t a_off = (uint32_t)(((warp_m * 64 + (lane & 15)) * LDH
                                       + (lane >> 4) * 8) * 2);
    const uint32_t b_off = (uint32_t)(((warp_n * 32 + (lane & 7)
                                        + ((lane >> 4) & 1) * 8) * LDH
                                       + ((lane >> 3) & 1) * 8) * 2);

    float acc[4][4][4];
#pragma unroll
    for (int mi = 0; mi < 4; mi++)
#pragma unroll
        for (int ni = 0; ni < 4; ni++)
#pragma unroll
            for (int k = 0; k < 4; k++) acc[mi][ni][k] = 0.0f;

    // Prefill STAGES-1 tiles (one free slot for single-barrier rotation)
#pragma unroll
    for (int s = 0; s < STAGES - 1; s++) {
        uint32_t sA = sbase + (uint32_t)(s * STAGE_HALVES) * 2;
        load_stage(A, W, m0, n0, s, sA, sA + 128 * LDH * 2, tid);
        cpa_commit();
    }

    for (int kt = 0; kt < NKT; kt++) {
        asm volatile("cp.async.wait_group %0;" :: "n"(STAGES - 2));
        __syncthreads();

        const int wt = kt + STAGES - 1;
        if (wt < NKT) {
            const int ws = wt % STAGES;
            uint32_t sA = sbase + (uint32_t)(ws * STAGE_HALVES) * 2;
            load_stage(A, W, m0, n0, wt, sA, sA + 128 * LDH * 2, tid);
        }
        cpa_commit();

        const int s = kt % STAGES;
        const uint32_t As_u = sbase + (uint32_t)(s * STAGE_HALVES) * 2;
        const uint32_t Bs_u = As_u + 128 * LDH * 2;

#pragma unroll
        for (int ks = 0; ks < 4; ks++) {       // 4 x k16
            uint32_t a[4][4], b[4][2];
#pragma unroll
            for (int mi = 0; mi < 4; mi++)
                ldsm4(a[mi][0], a[mi][1], a[mi][2], a[mi][3],
                      As_u + a_off + (uint32_t)((mi * 16 * LDH + ks * 16) * 2));
#pragma unroll
            for (int bp = 0; bp < 2; bp++)
                ldsm4(b[2 * bp][0], b[2 * bp][1], b[2 * bp + 1][0],
                      b[2 * bp + 1][1],
                      Bs_u + b_off + (uint32_t)((bp * 16 * LDH + ks * 16) * 2));
#pragma unroll
            for (int mi = 0; mi < 4; mi++)
#pragma unroll
                for (int ni = 0; ni < 4; ni++)
                    mma_f16(acc[mi][ni], a[mi], b[ni]);
        }
    }

    if (SPLIT) {
        // ---- smem-staged, coalesced epilogue ----
        __syncthreads();   // all LDSM reads of pipeline smem done
        const int bb = m0 >> 11;          // BM=128 divides T_SEQ
        const int t0 = m0 & (T_SEQ - 1);
        const int h0 = n0 >> 6;           // 2 heads per tile

        if (z < 2) {
            // stage [m][n] halves, pad LDO
#pragma unroll
            for (int mi = 0; mi < 4; mi++)
#pragma unroll
                for (int ni = 0; ni < 4; ni++)
#pragma unroll
                    for (int half_i = 0; half_i < 2; half_i++) {
                        const int ml = warp_m * 64 + mi * 16 + lr + half_i * 8;
                        const int nl = warp_n * 32 + ni * 8 + lc * 2;
                        *(__half2*)&smem[ml * LDO + nl] =
                            __floats2half2_rn(acc[mi][ni][half_i * 2],
                                              acc[mi][ni][half_i * 2 + 1]);
                    }
            __syncthreads();
            // coalesced: 8 threads per 128B head-row
            __half* Ch = (__half*)C;
#pragma unroll
            for (int p = 0; p < 8; p++) {
                int i = tid + p * 256;
                int c  = i & 7;
                int h2 = (i >> 3) & 1;
                int t  = i >> 4;
                uint4 val = *(uint4*)&smem[t * LDO + h2 * 64 + c * 8];
                __half* dst = Ch + (((size_t)(bb * NH + h0 + h2) * T_SEQ
                                     + t0 + t) * HD + c * 8);
                *(uint4*)dst = val;
            }
        } else {
            // stage TRANSPOSED [n][m], pad LDO
#pragma unroll
            for (int mi = 0; mi < 4; mi++)
#pragma unroll
                for (int ni = 0; ni < 4; ni++)
#pragma unroll
                    for (int half_i = 0; half_i < 2; half_i++) {
                        const int ml = warp_m * 64 + mi * 16 + lr + half_i * 8;
                        const int nl = warp_n * 32 + ni * 8 + lc * 2;
                        smem[nl * LDO + ml] =
                            __float2half_rn(acc[mi][ni][half_i * 2]);
                        smem[(nl + 1) * LDO + ml] =
                            __float2half_rn(acc[mi][ni][half_i * 2 + 1]);
                    }
            __syncthreads();
            // coalesced: 16B chunks along T per (head, d)
            __half* Vt = (__half*)C;
#pragma unroll
            for (int p = 0; p < 8; p++) {
                int i = tid + p * 256;
                int c  = i & 15;
                int dn = i >> 4;          // 0..127
                int h2 = dn >> 6;
                int d  = dn & 63;
                uint4 val = *(uint4*)&smem[dn * LDO + c * 8];
                __half* dst = Vt + (((size_t)(bb * NH + h0 + h2) * HD + d)
                                    * T_SEQ + t0 + c * 8);
                *(uint4*)dst = val;
            }
        }
    } else {
#pragma unroll
        for (int mi = 0; mi < 4; mi++) {
#pragma unroll
            for (int ni = 0; ni < 4; ni++) {
                const int n = n0 + warp_n * 32 + ni * 8 + lc * 2;
#pragma unroll
                for (int half_i = 0; half_i < 2; half_i++) {
                    const int mg = m0 + warp_m * 64 + mi * 16 + lr + half_i * 8;
                    float v0 = acc[mi][ni][half_i * 2 + 0];
                    float v1 = acc[mi][ni][half_i * 2 + 1];
                    if (BIAS) { v0 += bias[n]; v1 += bias[n + 1]; }
                    float* dst = (float*)C + (size_t)mg * DMODEL + n;
                    *(float2*)dst = make_float2(v0, v1);
                }
            }
        }
    }
}

// ---------------------------------------------------------------------------
// Tensor-core flash attention (causal), fp16, ldmatrix fragment loads
// ---------------------------------------------------------------------------
__device__ __forceinline__ void fa_load_kv(const __half* __restrict__ Kh,
                                           const __half* __restrict__ Vtg,
                                           uint32_t ks, uint32_t vs,
                                           size_t hb, size_t vb, int j0, int tid)
{
#pragma unroll
    for (int p = 0; p < 4; p++) {
        int i = p * 128 + tid;
        int r = i >> 3, c = i & 7;
        cpa16(ks + (uint32_t)(r * 144 + c * 16),
              Kh + hb + (size_t)(j0 + r) * HD + c * 8);
    }
#pragma unroll
    for (int p = 0; p < 4; p++) {
        int i = p * 128 + tid;
        int d = i >> 3, c = i & 7;
        cpa16(vs + (uint32_t)(d * 144 + c * 16),
              Vtg + vb + (size_t)d * T_SEQ + j0 + c * 8);
    }
}

__global__ void __launch_bounds__(128, 4)
flash_attn_tc(const __half* __restrict__ Qh, const __half* __restrict__ Kh,
              const __half* __restrict__ Vtg, __half* __restrict__ ctx)
{
    extern __shared__ __align__(16) char sm[];

    const int qt = (T_SEQ / 64 - 1) - blockIdx.x;   // heavy first
    const int h  = blockIdx.y;
    const int b  = blockIdx.z;
    const int i0 = qt * 64;
    const size_t hb = ((size_t)(b * NH + h)) * T_SEQ * HD;
    const size_t vb = ((size_t)(b * NH + h)) * HD * T_SEQ;

    const int tid  = threadIdx.x;
    const int wid  = tid >> 5;
    const int lane = tid & 31;
    const int lr = lane >> 2;
    const int lc = lane & 3;

    const uint32_t Qs_u  = smem_u32(sm) + FA_QS;
    const uint32_t Ks_u0 = smem_u32(sm) + FA_KS0;
    const uint32_t Vs_u0 = smem_u32(sm) + FA_VS0;

    const uint32_t qa_off = (uint32_t)(((wid * 16 + (lane & 15)) * 72
                                        + (lane >> 4) * 8) * 2);
    const uint32_t kb_off = (uint32_t)((((lane & 7) + ((lane >> 4) & 1) * 8) * 72
                                        + ((lane >> 3) & 1) * 8) * 2);

    // Prologue: Q tile + KV tile 0
    {
#pragma unroll
        for (int p = 0; p < 4; p++) {
            int i = p * 128 + tid;
            int r = i >> 3, c = i & 7;
            cpa16(Qs_u + (uint32_t)(r * 144 + c * 16),
                  Qh + hb + (size_t)(i0 + r) * HD + c * 8);
        }
        fa_load_kv(Kh, Vtg, Ks_u0, Vs_u0, hb, vb, 0, tid);
        cpa_commit();
    }

    float m0 = -1e30f, m1 = -1e30f, l0 = 0.0f, l1 = 0.0f;
    float o[8][4];
#pragma unroll
    for (int nf = 0; nf < 8; nf++)
#pragma unroll
        for (int j = 0; j < 4; j++) o[nf][j] = 0.0f;

    const int qr = wid * 16 + lr;
    const float kk = 0.18033688011112042f;  // log2(e)/sqrt(64)

    for (int jt = 0; jt <= qt; jt++) {
        if (jt < qt) {
            const int nb = (jt + 1) & 1;
            fa_load_kv(Kh, Vtg, Ks_u0 + nb * 9216, Vs_u0 + nb * 9216,
                       hb, vb, (jt + 1) * 64, tid);
        }
        cpa_commit();
        asm volatile("cp.async.wait_group 1;");
        __syncthreads();

        const uint32_t Ks_u = Ks_u0 + (jt & 1) * 9216;
        const uint32_t Vs_u = Vs_u0 + (jt & 1) * 9216;

        // ---- S = Q @ K^T ----
        float s[8][4];
#pragma unroll
        for (int nf = 0; nf < 8; nf++)
#pragma unroll
            for (int j = 0; j < 4; j++) s[nf][j] = 0.0f;

#pragma unroll
        for (int kc = 0; kc < 4; kc++) {
            uint32_t a[4];
            ldsm4(a[0], a[1], a[2], a[3], Qs_u + qa_off + kc * 32);
#pragma unroll
            for (int np = 0; np < 4; np++) {
                uint32_t b0, b1, b2, b3;
                ldsm4(b0, b1, b2, b3,
                      Ks_u + kb_off + (uint32_t)((np * 16 * 72 + kc * 16) * 2));
                uint32_t bl[2] = { b0, b1 };
                uint32_t bh[2] = { b2, b3 };
                mma_f16(s[2 * np],     a, bl);
                mma_f16(s[2 * np + 1], a, bh);
            }
        }

        // ---- online softmax (exp2 domain) ----
        const bool diag = (jt == qt);
        float mx0 = -1e30f, mx1 = -1e30f;
#pragma unroll
        for (int nf = 0; nf < 8; nf++) {
            float e0 = s[nf][0] * kk, e1 = s[nf][1] * kk;
            float e2 = s[nf][2] * kk, e3 = s[nf][3] * kk;
            if (diag) {
                const int c0 = nf * 8 + lc * 2, c1 = c0 + 1;
                if (c0 > qr)     e0 = -1e30f;
                if (c1 > qr)     e1 = -1e30f;
                if (c0 > qr + 8) e2 = -1e30f;
                if (c1 > qr + 8) e3 = -1e30f;
            }
            s[nf][0] = e0; s[nf][1] = e1; s[nf][2] = e2; s[nf][3] = e3;
            mx0 = fmaxf(mx0, fmaxf(e0, e1));
            mx1 = fmaxf(mx1, fmaxf(e2, e3));
        }
        mx0 = fmaxf(mx0, __shfl_xor_sync(0xffffffffu, mx0, 1));
        mx0 = fmaxf(mx0, __shfl_xor_sync(0xffffffffu, mx0, 2));
        mx1 = fmaxf(mx1, __shfl_xor_sync(0xffffffffu, mx1, 1));
        mx1 = fmaxf(mx1, __shfl_xor_sync(0xffffffffu, mx1, 2));

        const float mn0 = fmaxf(m0, mx0), mn1 = fmaxf(m1, mx1);
        const float al0 = ex2(m0 - mn0),  al1 = ex2(m1 - mn1);

        uint32_t ph[8][2];
        float sum0 = 0.0f, sum1 = 0.0f;
#pragma unroll
        for (int nf = 0; nf < 8; nf++) {
            float p0 = ex2(s[nf][0] - mn0), p1 = ex2(s[nf][1] - mn0);
            float p2 = ex2(s[nf][2] - mn1), p3 = ex2(s[nf][3] - mn1);
            sum0 += p0 + p1;
            sum1 += p2 + p3;
            __half2 hlo = __floats2half2_rn(p0, p1);
            __half2 hhi = __floats2half2_rn(p2, p3);
            ph[nf][0] = *(uint32_t*)&hlo;
            ph[nf][1] = *(uint32_t*)&hhi;
        }
        sum0 += __shfl_xor_sync(0xffffffffu, sum0, 1);
        sum0 += __shfl_xor_sync(0xffffffffu, sum0, 2);
        sum1 += __shfl_xor_sync(0xffffffffu, sum1, 1);
        sum1 += __shfl_xor_sync(0xffffffffu, sum1, 2);
        l0 = l0 * al0 + sum0;
        l1 = l1 * al1 + sum1;
        m0 = mn0; m1 = mn1;
#pragma unroll
        for (int nf = 0; nf < 8; nf++) {
            o[nf][0] *= al0; o[nf][1] *= al0;
            o[nf][2] *= al1; o[nf][3] *= al1;
        }

        // ---- O += P @ V ----
#pragma unroll
        for (int kc = 0; kc < 4; kc++) {
            uint32_t a[4] = { ph[2 * kc][0], ph[2 * kc][1],
                              ph[2 * kc + 1][0], ph[2 * kc + 1][1] };
#pragma unroll
            for (int np = 0; np < 4; np++) {
                uint32_t b0, b1, b2, b3;
                ldsm4(b0, b1, b2, b3,
                      Vs_u + kb_off + (uint32_t)((np * 16 * 72 + kc * 16) * 2));
                uint32_t bl[2] = { b0, b1 };
                uint32_t bh[2] = { b2, b3 };
                mma_f16(o[2 * np],     a, bl);
                mma_f16(o[2 * np + 1], a, bh);
            }
        }
        __syncthreads();
    }

    // ---- epilogue ----
    const float inv0 = 1.0f / l0, inv1 = 1.0f / l1;
    const int t_lo = i0 + qr;
#pragma unroll
    for (int nf = 0; nf < 8; nf++) {
        const int d = nf * 8 + lc * 2;
        __half* p0 = ctx + ((size_t)(b * T_SEQ + t_lo)) * DMODEL + h * HD + d;
        *(__half2*)p0 = __floats2half2_rn(o[nf][0] * inv0, o[nf][1] * inv0);
        __half* p1 = p0 + (size_t)8 * DMODEL;
        *(__half2*)p1 = __floats2half2_rn(o[nf][2] * inv1, o[nf][3] * inv1);
    }
}

// ---------------------------------------------------------------------------

extern "C" void kernel_launch(void* const* d_in, const int* in_sizes, int n_in,
                              void* d_out, int out_size)
{
    const float* x  = (const float*)d_in[0];
    const float* wq = (const float*)d_in[1];
    const float* wk = (const float*)d_in[2];
    const float* wv = (const float*)d_in[3];
    const float* wo = (const float*)d_in[4];
    const float* bo = (const float*)d_in[5];
    float* out = (float*)d_out;

    __half *pXh, *pWh, *pQh, *pKh, *pVt, *pCtx;
    cudaGetSymbolAddress((void**)&pXh, g_xh);
    cudaGetSymbolAddress((void**)&pWh, g_wh);
    cudaGetSymbolAddress((void**)&pQh, g_Qh);
    cudaGetSymbolAddress((void**)&pKh, g_Kh);
    cudaGetSymbolAddress((void**)&pVt, g_Vt);
    cudaGetSymbolAddress((void**)&pCtx, g_ctxh);

    __half* pWq = pWh;
    __half* pWk = pWh + (size_t)DMODEL * DMODEL;
    __half* pWv = pWh + 2 * (size_t)DMODEL * DMODEL;
    __half* pWo = pWh + 3 * (size_t)DMODEL * DMODEL;

    cudaFuncSetAttribute(gemm_fp16<true, false>,
                         cudaFuncAttributeMaxDynamicSharedMemorySize, GEMM_SMEM);
    cudaFuncSetAttribute(gemm_fp16<false, true>,
                         cudaFuncAttributeMaxDynamicSharedMemorySize, GEMM_SMEM);
    cudaFuncSetAttribute(flash_attn_tc,
                         cudaFuncAttributeMaxDynamicSharedMemorySize, FA_SMEM);

    // 1) single-launch f32->fp16 conversion (x + 4 weights)
    {
        int total = XN4 + 4 * WN4;
        cvt_all<<<total / 256, 256>>>(
            (const float4*)x, (const float4*)wq, (const float4*)wk,
            (const float4*)wv, (const float4*)wo, (uint2*)pXh, (uint2*)pWh);
    }

    // 2) fused QKV projections (fp16 MMA); Q/K split-head, V transposed
    {
        dim3 grid(DMODEL / BN, M_ROWS / BM, 3);
        gemm_fp16<true, false><<<grid, 256, GEMM_SMEM>>>(
            pXh, pWq, pWk, pWv, pQh, pKh, pVt, nullptr);
    }

    // 3) tensor-core flash attention (fp16)
    {
        dim3 fgrid(T_SEQ / 64, NH, BATCH_N);
        flash_attn_tc<<<fgrid, 128, FA_SMEM>>>(pQh, pKh, pVt, pCtx);
    }

    // 4) output projection + bias (fp32 out)
    {
        dim3 grid(DMODEL / BN, M_ROWS / BM, 1);
        gemm_fp16<false, true><<<grid, 256, GEMM_SMEM>>>(
            pCtx, pWo, pWo, pWo, out, out, out, bo);
    }
}